// round 12
// baseline (speedup 1.0000x reference)
#include <cuda_runtime.h>
#include <math.h>
#include <stdint.h>

#define TLEN  32000
#define BATCH 8
#define RES   32
#define SKIPC 32
#define TT    128
#define TLT   256   // threads for k_layer (8 warps)

typedef unsigned long long ull;

// ==================== helpers ==============================================
__device__ __forceinline__ uint32_t smem_u32(const void* p) {
    uint32_t a;
    asm("{ .reg .u64 t; cvta.to.shared.u64 t, %1; cvt.u32.u64 %0, t; }" : "=r"(a) : "l"(p));
    return a;
}
__device__ __forceinline__ void sts32(uint32_t a, uint32_t v) {
    asm volatile("st.shared.b32 [%0], %1;" :: "r"(a), "r"(v));
}
__device__ __forceinline__ void ldsm4(uint32_t& r0, uint32_t& r1, uint32_t& r2, uint32_t& r3,
                                      uint32_t addr) {
    asm volatile("ldmatrix.sync.aligned.m8n8.x4.shared.b16 {%0,%1,%2,%3}, [%4];"
                 : "=r"(r0), "=r"(r1), "=r"(r2), "=r"(r3) : "r"(addr));
}
// pack {lo=v0, hi=v1} as bf16x2 (RN)
__device__ __forceinline__ uint32_t pack_bf16x2(float v0, float v1) {
    uint32_t r;
    asm("cvt.rn.bf16x2.f32 %0, %1, %2;" : "=r"(r) : "f"(v1), "f"(v0));
    return r;
}
__device__ __forceinline__ void mma_bf16(float* c,
                                         uint32_t a0, uint32_t a1, uint32_t a2, uint32_t a3,
                                         uint32_t b0, uint32_t b1) {
    asm volatile("mma.sync.aligned.m16n8k16.row.col.f32.bf16.bf16.f32 "
                 "{%0,%1,%2,%3}, {%4,%5,%6,%7}, {%8,%9}, {%0,%1,%2,%3};"
                 : "+f"(c[0]), "+f"(c[1]), "+f"(c[2]), "+f"(c[3])
                 : "r"(a0), "r"(a1), "r"(a2), "r"(a3), "r"(b0), "r"(b1));
}
__device__ __forceinline__ float ftanh(float x) {
    float e = __expf(-2.f * fabsf(x));
    float r = __fdividef(1.f - e, 1.f + e);
    return copysignf(r, x);
}
__device__ __forceinline__ float fsigm(float x) {
    return __fdividef(1.f, 1.f + __expf(-x));
}
// split pair into bf16 hi pack + residual lo pack
__device__ __forceinline__ void split_pair(float v0, float v1, uint32_t& hi, uint32_t& lo) {
    hi = pack_bf16x2(v0, v1);
    float h0 = __uint_as_float((hi & 0xFFFFu) << 16);
    float h1 = __uint_as_float(hi & 0xFFFF0000u);
    lo = pack_bf16x2(v0 - h0, v1 - h1);
}
__device__ __forceinline__ float bfl(uint32_t x) { return __uint_as_float(x << 16); }
__device__ __forceinline__ float bfh(uint32_t x) { return __uint_as_float(x & 0xFFFF0000u); }

// ==================== device scratch =======================================
__device__ uint32_t g_bh0[BATCH * TLEN * 16];
__device__ uint32_t g_bl0[BATCH * TLEN * 16];
__device__ uint32_t g_bh1[BATCH * TLEN * 16];
__device__ uint32_t g_bl1[BATCH * TLEN * 16];
__device__ float g_skip[BATCH * TLEN * SKIPC];   // time-major [b][t][32]
__device__ float g_ts[BATCH * SKIPC * TLEN];     // channel-major for post conv
__device__ float g_p2[BATCH * 16 * TLEN];
__device__ float g_p3[BATCH * 8 * TLEN];
__device__ float g_p4[BATCH * 1 * TLEN];
__device__ uint32_t g_w1h[10][64 * 52];
__device__ uint32_t g_w1l[10][64 * 52];
__device__ uint32_t g_w2h[10][64 * 20];
__device__ uint32_t g_w2l[10][64 * 20];

// ==================== weight prep ==========================================
__global__ __launch_bounds__(TT) void k_wprep(const float* __restrict__ res_w1,
                                              const float* __restrict__ res_w2) {
    int L = blockIdx.x;
    const float* w1 = res_w1 + (size_t)L * 64 * 32 * 3;
    const float* w2 = res_w2 + (size_t)L * 64 * 32;
    int tid = threadIdx.x;
    for (int i = tid; i < 64 * 48; i += TT) {
        int oc = i / 48, pj = i % 48;
        int k0 = 2 * pj;
        int tap = k0 >> 5, ic = k0 & 31;
        float v0 = w1[oc * 96 + ic * 3 + tap];
        float v1 = w1[oc * 96 + (ic + 1) * 3 + tap];
        uint32_t hi, lo;
        split_pair(v0, v1, hi, lo);
        g_w1h[L][oc * 52 + pj] = hi;
        g_w1l[L][oc * 52 + pj] = lo;
    }
    for (int i = tid; i < 64 * 16; i += TT) {
        int oc = i / 16, icp = i % 16;
        float v0 = w2[oc * 32 + 2 * icp];
        float v1 = w2[oc * 32 + 2 * icp + 1];
        uint32_t hi, lo;
        split_pair(v0, v1, hi, lo);
        g_w2h[L][oc * 20 + icp] = hi;
        g_w2l[L][oc * 20 + icp] = lo;
    }
}

// ==================== front conv -> bf16 hi/lo t-major; zero skip ==========
__global__ __launch_bounds__(TT) void k_front(const float* __restrict__ x,
                                              const float* __restrict__ w) {
    int b = blockIdx.y;
    int t = blockIdx.x * TT + threadIdx.x;
    if (t >= TLEN) return;
    const float* xb = x + b * TLEN;
    float x0 = xb[t];
    float x1 = (t >= 1) ? xb[t - 1] : 0.f;
    float x2 = (t >= 2) ? xb[t - 2] : 0.f;
    size_t base = (size_t)(b * TLEN + t) * 16;
    float* sk = g_skip + (size_t)(b * TLEN + t) * 32;
#pragma unroll
    for (int p = 0; p < 16; p++) {
        int oc = 2 * p;
        float v0 = fmaf(w[oc * 3 + 0], x2, fmaf(w[oc * 3 + 1], x1, w[oc * 3 + 2] * x0));
        float v1 = fmaf(w[(oc + 1) * 3 + 0], x2,
                   fmaf(w[(oc + 1) * 3 + 1], x1, w[(oc + 1) * 3 + 2] * x0));
        uint32_t hi, lo;
        split_pair(v0, v1, hi, lo);
        g_bh0[base + p] = hi;
        g_bl0[base + p] = lo;
        sk[oc] = 0.f;
        sk[oc + 1] = 0.f;
    }
}

// ==================== residual layer =======================================
#define STRA 208
#define STRG 80
#define SO_AH 0
#define SO_AL (SO_AH + 128 * STRA)       // 26624
#define SO_BH (SO_AL + 128 * STRA)       // 53248
#define SO_BL (SO_BH + 64 * STRA)        // 66560
#define SO_W2H (SO_BL + 64 * STRA)       // 79872
#define SO_W2L (SO_W2H + 64 * STRG)      // 84992
#define SMEM_LAYER_BYTES (SO_W2L + 64 * STRG)  // 90112

// fused 3-combo conv GEMM: acc += AH·BH^T + AL·BH^T + AH·BL^T
__device__ __forceinline__ void gemm_fused(uint32_t aHB, uint32_t aLB,
                                           uint32_t bHB, uint32_t bLB,
                                           int stride, int nk16, float acc[8][4],
                                           int wid, int lid) {
    int lr = lid & 7;
    int aRowOff = lr + ((lid >> 3) & 1) * 8;
    int aKOff = (lid >> 4) * 8;
    int bRowOff = lr + (lid >> 4) * 8;
    int bKOff = ((lid >> 3) & 1) * 8;
    uint32_t aH = aHB + (uint32_t)((16 * wid + aRowOff) * stride + aKOff * 2);
    uint32_t aL = aLB + (uint32_t)((16 * wid + aRowOff) * stride + aKOff * 2);
    uint32_t bH0 = bHB + (uint32_t)(bRowOff * stride + bKOff * 2);
    uint32_t bL0 = bLB + (uint32_t)(bRowOff * stride + bKOff * 2);
#pragma unroll
    for (int k = 0; k < nk16; k++) {
        uint32_t ka = (uint32_t)(k * 32);
        uint32_t ah0, ah1, ah2, ah3, al0, al1, al2, al3;
        ldsm4(ah0, ah1, ah2, ah3, aH + ka);
        ldsm4(al0, al1, al2, al3, aL + ka);
#pragma unroll
        for (int np = 0; np < 4; np++) {
            uint32_t off = (uint32_t)(16 * np * stride) + ka;
            uint32_t bh0, bh1, bh2, bh3, bl0, bl1, bl2, bl3;
            ldsm4(bh0, bh1, bh2, bh3, bH0 + off);
            ldsm4(bl0, bl1, bl2, bl3, bL0 + off);
            mma_bf16(acc[2 * np],     ah0, ah1, ah2, ah3, bh0, bh1);
            mma_bf16(acc[2 * np + 1], ah0, ah1, ah2, ah3, bh2, bh3);
            mma_bf16(acc[2 * np],     al0, al1, al2, al3, bh0, bh1);
            mma_bf16(acc[2 * np + 1], al0, al1, al2, al3, bh2, bh3);
            mma_bf16(acc[2 * np],     ah0, ah1, ah2, ah3, bl0, bl1);
            mma_bf16(acc[2 * np + 1], ah0, ah1, ah2, ah3, bl2, bl3);
        }
    }
}

__global__ __launch_bounds__(TLT, 2) void k_layer(const uint32_t* __restrict__ hinH,
                                                  const uint32_t* __restrict__ hinL,
                                                  uint32_t* __restrict__ houtH,
                                                  uint32_t* __restrict__ houtL,
                                                  const uint32_t* __restrict__ w1h,
                                                  const uint32_t* __restrict__ w1l,
                                                  const uint32_t* __restrict__ w2h,
                                                  const uint32_t* __restrict__ w2l,
                                                  int d) {
    extern __shared__ __align__(16) char smem[];
    uint32_t sb = smem_u32(smem);
    int tid = threadIdx.x;
    int wid = tid >> 5;
    int lid = tid & 31;
    int qr = lid >> 2;
    int qc = lid & 3;
    int b = blockIdx.y;
    int t0 = blockIdx.x * 128;

    // ---- stage A: vectorized copy; 768 copy-units of 64B (row,tap,arr)
    {
        const uint4 zero4 = make_uint4(0, 0, 0, 0);
#pragma unroll
        for (int u = 0; u < 3; u++) {
            int idx = tid + u * TLT;
            int m = idx / 6;
            int j = idx % 6;
            int tap = j >> 1;
            int arr = j & 1;
            int tt = t0 + m - (2 - tap) * d;
            uint32_t dst = (uint32_t)((arr ? SO_AL : SO_AH) + m * STRA + tap * 64);
            if (tt >= 0) {
                const uint32_t* src = (arr ? hinL : hinH) + (size_t)(b * TLEN + tt) * 16;
                const uint4* s4 = reinterpret_cast<const uint4*>(src);
#pragma unroll
                for (int q = 0; q < 4; q++)
                    *reinterpret_cast<uint4*>(smem + dst + q * 16) = s4[q];
            } else {
#pragma unroll
                for (int q = 0; q < 4; q++)
                    *reinterpret_cast<uint4*>(smem + dst + q * 16) = zero4;
            }
        }
    }
    // ---- weights: linear uint4 copies
    {
        const uint4* s1h = reinterpret_cast<const uint4*>(w1h);
        const uint4* s1l = reinterpret_cast<const uint4*>(w1l);
        uint4* d1h = reinterpret_cast<uint4*>(smem + SO_BH);
        uint4* d1l = reinterpret_cast<uint4*>(smem + SO_BL);
        for (int i = tid; i < 64 * 13; i += TLT) {
            d1h[i] = s1h[i];
            d1l[i] = s1l[i];
        }
        const uint4* s2h = reinterpret_cast<const uint4*>(w2h);
        const uint4* s2l = reinterpret_cast<const uint4*>(w2l);
        uint4* d2h = reinterpret_cast<uint4*>(smem + SO_W2H);
        uint4* d2l = reinterpret_cast<uint4*>(smem + SO_W2L);
        for (int i = tid; i < 64 * 5; i += TLT) {
            d2h[i] = s2h[i];
            d2l[i] = s2l[i];
        }
    }
    __syncthreads();

    // ---- conv GEMM: fused 3-combo
    float acc[8][4];
#pragma unroll
    for (int n = 0; n < 8; n++)
#pragma unroll
        for (int j = 0; j < 4; j++) acc[n][j] = 0.f;

    gemm_fused(sb + SO_AH, sb + SO_AL, sb + SO_BH, sb + SO_BL, STRA, 6, acc, wid, lid);

    // ---- gating entirely in registers -> A fragments for the 1x1 GEMM
    float gv[4][4];
#pragma unroll
    for (int n = 0; n < 4; n++)
#pragma unroll
        for (int j = 0; j < 4; j++)
            gv[n][j] = ftanh(acc[n][j]) * fsigm(acc[n + 4][j]);

    uint32_t aH[2][4], aL[2][4];
#pragma unroll
    for (int kk = 0; kk < 2; kk++) {
        split_pair(gv[2 * kk][0],     gv[2 * kk][1],     aH[kk][0], aL[kk][0]);
        split_pair(gv[2 * kk][2],     gv[2 * kk][3],     aH[kk][1], aL[kk][1]);
        split_pair(gv[2 * kk + 1][0], gv[2 * kk + 1][1], aH[kk][2], aL[kk][2]);
        split_pair(gv[2 * kk + 1][2], gv[2 * kk + 1][3], aH[kk][3], aL[kk][3]);
    }

    // ---- 1x1 GEMM: A from registers, B (W2) via ldmatrix; 3 combos
    float acc2[8][4];
#pragma unroll
    for (int n = 0; n < 8; n++)
#pragma unroll
        for (int j = 0; j < 4; j++) acc2[n][j] = 0.f;
    {
        int lr = lid & 7;
        int bRowOff = lr + (lid >> 4) * 8;
        int bKOff = ((lid >> 3) & 1) * 8;
        uint32_t w2H0 = sb + SO_W2H + (uint32_t)(bRowOff * STRG + bKOff * 2);
        uint32_t w2L0 = sb + SO_W2L + (uint32_t)(bRowOff * STRG + bKOff * 2);
#pragma unroll
        for (int kk = 0; kk < 2; kk++) {
            uint32_t ka = (uint32_t)(kk * 32);
#pragma unroll
            for (int np = 0; np < 4; np++) {
                uint32_t off = (uint32_t)(16 * np * STRG) + ka;
                uint32_t bh0, bh1, bh2, bh3, bl0, bl1, bl2, bl3;
                ldsm4(bh0, bh1, bh2, bh3, w2H0 + off);
                ldsm4(bl0, bl1, bl2, bl3, w2L0 + off);
                mma_bf16(acc2[2 * np],     aH[kk][0], aH[kk][1], aH[kk][2], aH[kk][3], bh0, bh1);
                mma_bf16(acc2[2 * np + 1], aH[kk][0], aH[kk][1], aH[kk][2], aH[kk][3], bh2, bh3);
                mma_bf16(acc2[2 * np],     aL[kk][0], aL[kk][1], aL[kk][2], aL[kk][3], bh0, bh1);
                mma_bf16(acc2[2 * np + 1], aL[kk][0], aL[kk][1], aL[kk][2], aL[kk][3], bh2, bh3);
                mma_bf16(acc2[2 * np],     aH[kk][0], aH[kk][1], aH[kk][2], aH[kk][3], bl0, bl1);
                mma_bf16(acc2[2 * np + 1], aH[kk][0], aH[kk][1], aH[kk][2], aH[kk][3], bl2, bl3);
            }
        }
    }

    // ---- epilogue: residual from A(tap2) + z -> hout; skip (t-major) += z
#pragma unroll
    for (int rh = 0; rh < 2; rh++) {
        int rowA = 16 * wid + qr + 8 * rh;
        int t = t0 + rowA;
        size_t obase = (size_t)(b * TLEN + t) * 16;
        float2* sk = reinterpret_cast<float2*>(g_skip + (size_t)(b * TLEN + t) * 32);
#pragma unroll
        for (int n = 0; n < 4; n++) {
            int c = 8 * n + 2 * qc;
            uint32_t hh = *reinterpret_cast<uint32_t*>(smem + SO_AH + rowA * STRA + (64 + c) * 2);
            uint32_t ll = *reinterpret_cast<uint32_t*>(smem + SO_AL + rowA * STRA + (64 + c) * 2);
            float r0 = bfl(hh) + bfl(ll) + acc2[n][2 * rh + 0];
            float r1 = bfh(hh) + bfh(ll) + acc2[n][2 * rh + 1];
            uint32_t hi, lo;
            split_pair(r0, r1, hi, lo);
            houtH[obase + (c >> 1)] = hi;
            houtL[obase + (c >> 1)] = lo;
        }
#pragma unroll
        for (int n = 4; n < 8; n++) {
            int c = 8 * (n - 4) + 2 * qc;
            float2 v = sk[c >> 1];
            v.x += acc2[n][2 * rh + 0];
            v.y += acc2[n][2 * rh + 1];
            sk[c >> 1] = v;
        }
    }
}

// ==================== tanh over skip (t-major -> channel-major) ============
__global__ __launch_bounds__(TT) void k_tanhskip() {
    int b = blockIdx.y;
    int t = blockIdx.x * TT + threadIdx.x;
    if (t >= TLEN) return;
    const float* sk = g_skip + (size_t)(b * TLEN + t) * 32;
#pragma unroll
    for (int c = 0; c < SKIPC; c++)
        g_ts[(b * SKIPC + c) * TLEN + t] = ftanh(sk[c]);
}

// ==================== generic causal k=3 conv + tanh =======================
template <int IC, int OC>
__global__ __launch_bounds__(TT) void k_conv3tanh(const float* __restrict__ in,
                                                  float* __restrict__ out,
                                                  const float* __restrict__ w) {
    __shared__ float ws[3][IC][OC];
    int tid = threadIdx.x;
    for (int i = tid; i < OC * IC * 3; i += TT) {
        int oc = i / (IC * 3), r = i % (IC * 3), ic = r / 3, k = r % 3;
        ws[k][ic][oc] = w[i];
    }
    __syncthreads();

    int b = blockIdx.y;
    int t = blockIdx.x * TT + tid;
    if (t >= TLEN) return;
    const float* ib = in + b * IC * TLEN;

    float acc[OC];
#pragma unroll
    for (int o = 0; o < OC; o++) acc[o] = 0.f;
#pragma unroll
    for (int k = 0; k < 3; k++) {
        int tt = t - (2 - k);
        if (tt >= 0) {
#pragma unroll
            for (int ic = 0; ic < IC; ic++) {
                float v = ib[ic * TLEN + tt];
#pragma unroll
                for (int o = 0; o < OC; o++)
                    acc[o] = fmaf(v, ws[k][ic][o], acc[o]);
            }
        }
    }
    float* ob = out + b * OC * TLEN;
#pragma unroll
    for (int o = 0; o < OC; o++)
        ob[o * TLEN + t] = ftanh(acc[o]);
}

// ==================== Volterra head ========================================
__global__ __launch_bounds__(TT) void k_vnn(const float* __restrict__ w1,
                                            const float* __restrict__ w2,
                                            float* __restrict__ out) {
    int b = blockIdx.y;
    int t = blockIdx.x * TT + threadIdx.x;
    if (t >= TLEN) return;
    const float* pb = g_p4 + b * TLEN;

    float pv[16];
#pragma unroll
    for (int k = 0; k < 16; k++) {
        int tt = t - (15 - k);
        pv[k] = (tt >= 0) ? pb[tt] : 0.f;
    }
    float lin = 0.f;
#pragma unroll
    for (int k = 0; k < 16; k++) lin = fmaf(w1[k], pv[k], lin);

    float x2[6];
#pragma unroll
    for (int j = 0; j < 6; j++) {
        float a = 0.f;
#pragma unroll
        for (int k = 0; k < 16; k++) a = fmaf(w2[j * 16 + k], pv[k], a);
        x2[j] = a;
    }
    float quad = x2[0] * x2[3] + x2[1] * x2[4] + x2[2] * x2[5];
    out[b * TLEN + t] = lin + quad;
}

// ==================== host launch ==========================================
extern "C" void kernel_launch(void* const* d_in, const int* in_sizes, int n_in,
                              void* d_out, int out_size) {
    const float* x       = (const float*)d_in[0];
    const float* conv1_w = (const float*)d_in[1];
    const float* res_w1  = (const float*)d_in[2];
    const float* res_w2  = (const float*)d_in[3];
    const float* post2_w = (const float*)d_in[4];
    const float* post3_w = (const float*)d_in[5];
    const float* post4_w = (const float*)d_in[6];
    const float* vnn1_w  = (const float*)d_in[7];
    const float* vnn2_w  = (const float*)d_in[8];
    float* out = (float*)d_out;

    uint32_t *bh0, *bl0, *bh1, *bl1;
    uint32_t *w1h, *w1l, *w2h, *w2l;
    float *tsp, *p2p, *p3p, *p4p;
    cudaGetSymbolAddress((void**)&bh0, g_bh0);
    cudaGetSymbolAddress((void**)&bl0, g_bl0);
    cudaGetSymbolAddress((void**)&bh1, g_bh1);
    cudaGetSymbolAddress((void**)&bl1, g_bl1);
    cudaGetSymbolAddress((void**)&w1h, g_w1h);
    cudaGetSymbolAddress((void**)&w1l, g_w1l);
    cudaGetSymbolAddress((void**)&w2h, g_w2h);
    cudaGetSymbolAddress((void**)&w2l, g_w2l);
    cudaGetSymbolAddress((void**)&tsp, g_ts);
    cudaGetSymbolAddress((void**)&p2p, g_p2);
    cudaGetSymbolAddress((void**)&p3p, g_p3);
    cudaGetSymbolAddress((void**)&p4p, g_p4);

    cudaFuncSetAttribute(k_layer, cudaFuncAttributeMaxDynamicSharedMemorySize,
                         SMEM_LAYER_BYTES);

    dim3 grid(TLEN / 128, BATCH);   // 250 x 8

    k_wprep<<<10, TT>>>(res_w1, res_w2);
    k_front<<<grid, TT>>>(x, conv1_w);

    const uint32_t *hinH = bh0, *hinL = bl0;
    uint32_t *houtH = bh1, *houtL = bl1;
    for (int s = 0; s < 2; s++) {
        for (int i = 0; i < 10; i++) {
            k_layer<<<grid, TLT, SMEM_LAYER_BYTES>>>(
                hinH, hinL, houtH, houtL,
                w1h + (size_t)i * 64 * 52, w1l + (size_t)i * 64 * 52,
                w2h + (size_t)i * 64 * 20, w2l + (size_t)i * 64 * 20,
                1 << i);
            const uint32_t* th = houtH; const uint32_t* tl = houtL;
            houtH = (uint32_t*)hinH; houtL = (uint32_t*)hinL;
            hinH = th; hinL = tl;
        }
    }

    k_tanhskip<<<grid, TT>>>();
    k_conv3tanh<32, 16><<<grid, TT>>>(tsp, p2p, post2_w);
    k_conv3tanh<16, 8><<<grid, TT>>>(p2p, p3p, post3_w);
    k_conv3tanh<8, 1><<<grid, TT>>>(p3p, p4p, post4_w);
    k_vnn<<<grid, TT>>>(vnn1_w, vnn2_w, out);
}

// round 13
// speedup vs baseline: 1.5858x; 1.5858x over previous
#include <cuda_runtime.h>
#include <math.h>
#include <stdint.h>

#define TLEN  32000
#define BATCH 8
#define RES   32
#define SKIPC 32
#define TT    128
#define TLT   256   // threads for k_layer (8 warps)

typedef unsigned long long ull;

// ==================== helpers ==============================================
__device__ __forceinline__ uint32_t smem_u32(const void* p) {
    uint32_t a;
    asm("{ .reg .u64 t; cvta.to.shared.u64 t, %1; cvt.u32.u64 %0, t; }" : "=r"(a) : "l"(p));
    return a;
}
__device__ __forceinline__ void sts32(uint32_t a, uint32_t v) {
    asm volatile("st.shared.b32 [%0], %1;" :: "r"(a), "r"(v));
}
__device__ __forceinline__ void sts64f(uint32_t a, float x, float y) {
    asm volatile("st.shared.v2.f32 [%0], {%1, %2};" :: "r"(a), "f"(x), "f"(y));
}
__device__ __forceinline__ void lds128(uint4& v, uint32_t a) {
    asm volatile("ld.shared.v4.b32 {%0,%1,%2,%3}, [%4];"
                 : "=r"(v.x), "=r"(v.y), "=r"(v.z), "=r"(v.w) : "r"(a));
}
__device__ __forceinline__ void ldsm4(uint32_t& r0, uint32_t& r1, uint32_t& r2, uint32_t& r3,
                                      uint32_t addr) {
    asm volatile("ldmatrix.sync.aligned.m8n8.x4.shared.b16 {%0,%1,%2,%3}, [%4];"
                 : "=r"(r0), "=r"(r1), "=r"(r2), "=r"(r3) : "r"(addr));
}
// pack {lo=v0, hi=v1} as bf16x2 (RN)
__device__ __forceinline__ uint32_t pack_bf16x2(float v0, float v1) {
    uint32_t r;
    asm("cvt.rn.bf16x2.f32 %0, %1, %2;" : "=r"(r) : "f"(v1), "f"(v0));
    return r;
}
__device__ __forceinline__ void mma_bf16(float* c,
                                         uint32_t a0, uint32_t a1, uint32_t a2, uint32_t a3,
                                         uint32_t b0, uint32_t b1) {
    asm volatile("mma.sync.aligned.m16n8k16.row.col.f32.bf16.bf16.f32 "
                 "{%0,%1,%2,%3}, {%4,%5,%6,%7}, {%8,%9}, {%0,%1,%2,%3};"
                 : "+f"(c[0]), "+f"(c[1]), "+f"(c[2]), "+f"(c[3])
                 : "r"(a0), "r"(a1), "r"(a2), "r"(a3), "r"(b0), "r"(b1));
}
__device__ __forceinline__ float ftanh(float x) {
    float e = __expf(-2.f * fabsf(x));
    float r = __fdividef(1.f - e, 1.f + e);
    return copysignf(r, x);
}
__device__ __forceinline__ float fsigm(float x) {
    return __fdividef(1.f, 1.f + __expf(-x));
}
// split pair into bf16 hi pack + residual lo pack
__device__ __forceinline__ void split_pair(float v0, float v1, uint32_t& hi, uint32_t& lo) {
    hi = pack_bf16x2(v0, v1);
    float h0 = __uint_as_float((hi & 0xFFFFu) << 16);
    float h1 = __uint_as_float(hi & 0xFFFF0000u);
    lo = pack_bf16x2(v0 - h0, v1 - h1);
}
__device__ __forceinline__ float bfl(uint32_t x) { return __uint_as_float(x << 16); }
__device__ __forceinline__ float bfh(uint32_t x) { return __uint_as_float(x & 0xFFFF0000u); }

// ==================== device scratch =======================================
__device__ uint32_t g_bh0[BATCH * TLEN * 16];
__device__ uint32_t g_bl0[BATCH * TLEN * 16];
__device__ uint32_t g_bh1[BATCH * TLEN * 16];
__device__ uint32_t g_bl1[BATCH * TLEN * 16];
__device__ float g_skip[BATCH * TLEN * SKIPC];   // time-major [b][t][32]
__device__ float g_ts[BATCH * SKIPC * TLEN];     // channel-major for post conv
__device__ float g_p2[BATCH * 16 * TLEN];
__device__ float g_p3[BATCH * 8 * TLEN];
__device__ float g_p4[BATCH * 1 * TLEN];
__device__ uint32_t g_w1h[10][64 * 52];
__device__ uint32_t g_w1l[10][64 * 52];
__device__ uint32_t g_w2h[10][64 * 20];
__device__ uint32_t g_w2l[10][64 * 20];

// ==================== weight prep ==========================================
__global__ __launch_bounds__(TT) void k_wprep(const float* __restrict__ res_w1,
                                              const float* __restrict__ res_w2) {
    int L = blockIdx.x;
    const float* w1 = res_w1 + (size_t)L * 64 * 32 * 3;
    const float* w2 = res_w2 + (size_t)L * 64 * 32;
    int tid = threadIdx.x;
    for (int i = tid; i < 64 * 48; i += TT) {
        int oc = i / 48, pj = i % 48;
        int k0 = 2 * pj;
        int tap = k0 >> 5, ic = k0 & 31;
        float v0 = w1[oc * 96 + ic * 3 + tap];
        float v1 = w1[oc * 96 + (ic + 1) * 3 + tap];
        uint32_t hi, lo;
        split_pair(v0, v1, hi, lo);
        g_w1h[L][oc * 52 + pj] = hi;
        g_w1l[L][oc * 52 + pj] = lo;
    }
    for (int i = tid; i < 64 * 16; i += TT) {
        int oc = i / 16, icp = i % 16;
        float v0 = w2[oc * 32 + 2 * icp];
        float v1 = w2[oc * 32 + 2 * icp + 1];
        uint32_t hi, lo;
        split_pair(v0, v1, hi, lo);
        g_w2h[L][oc * 20 + icp] = hi;
        g_w2l[L][oc * 20 + icp] = lo;
    }
}

// ==================== front conv -> bf16 hi/lo t-major; zero skip ==========
__global__ __launch_bounds__(TT) void k_front(const float* __restrict__ x,
                                              const float* __restrict__ w) {
    int b = blockIdx.y;
    int t = blockIdx.x * TT + threadIdx.x;
    if (t >= TLEN) return;
    const float* xb = x + b * TLEN;
    float x0 = xb[t];
    float x1 = (t >= 1) ? xb[t - 1] : 0.f;
    float x2 = (t >= 2) ? xb[t - 2] : 0.f;
    size_t base = (size_t)(b * TLEN + t) * 16;
    float* sk = g_skip + (size_t)(b * TLEN + t) * 32;
#pragma unroll
    for (int p = 0; p < 16; p++) {
        int oc = 2 * p;
        float v0 = fmaf(w[oc * 3 + 0], x2, fmaf(w[oc * 3 + 1], x1, w[oc * 3 + 2] * x0));
        float v1 = fmaf(w[(oc + 1) * 3 + 0], x2,
                   fmaf(w[(oc + 1) * 3 + 1], x1, w[(oc + 1) * 3 + 2] * x0));
        uint32_t hi, lo;
        split_pair(v0, v1, hi, lo);
        g_bh0[base + p] = hi;
        g_bl0[base + p] = lo;
        sk[oc] = 0.f;
        sk[oc + 1] = 0.f;
    }
}

// ==================== residual layer =======================================
#define STRA 208
#define STRG 80
#define SO_AH 0
#define SO_AL (SO_AH + 128 * STRA)       // 26624
#define SO_BH (SO_AL + 128 * STRA)       // 53248
#define SO_BL (SO_BH + 64 * STRA)        // 66560
#define SO_W2H (SO_BL + 64 * STRA)       // 79872
#define SO_W2L (SO_W2H + 64 * STRG)      // 84992
#define SMEM_LAYER_BYTES (SO_W2L + 64 * STRG)  // 90112
// exchange buffers (reuse of A/B space after epilogue sync)
#define EXH 0          // hout hi plane: 128 rows x 20 words (80B) = 10240
#define EXL 10240      // hout lo plane
#define EXS 20480      // skip z plane: 128 rows x 36 words (144B) = 18432

// fused 3-combo conv GEMM: acc += AH·BH^T + AL·BH^T + AH·BL^T
__device__ __forceinline__ void gemm_fused(uint32_t aHB, uint32_t aLB,
                                           uint32_t bHB, uint32_t bLB,
                                           int stride, int nk16, float acc[8][4],
                                           int wid, int lid) {
    int lr = lid & 7;
    int aRowOff = lr + ((lid >> 3) & 1) * 8;
    int aKOff = (lid >> 4) * 8;
    int bRowOff = lr + (lid >> 4) * 8;
    int bKOff = ((lid >> 3) & 1) * 8;
    uint32_t aH = aHB + (uint32_t)((16 * wid + aRowOff) * stride + aKOff * 2);
    uint32_t aL = aLB + (uint32_t)((16 * wid + aRowOff) * stride + aKOff * 2);
    uint32_t bH0 = bHB + (uint32_t)(bRowOff * stride + bKOff * 2);
    uint32_t bL0 = bLB + (uint32_t)(bRowOff * stride + bKOff * 2);
#pragma unroll
    for (int k = 0; k < nk16; k++) {
        uint32_t ka = (uint32_t)(k * 32);
        uint32_t ah0, ah1, ah2, ah3, al0, al1, al2, al3;
        ldsm4(ah0, ah1, ah2, ah3, aH + ka);
        ldsm4(al0, al1, al2, al3, aL + ka);
#pragma unroll
        for (int np = 0; np < 4; np++) {
            uint32_t off = (uint32_t)(16 * np * stride) + ka;
            uint32_t bh0, bh1, bh2, bh3, bl0, bl1, bl2, bl3;
            ldsm4(bh0, bh1, bh2, bh3, bH0 + off);
            ldsm4(bl0, bl1, bl2, bl3, bL0 + off);
            mma_bf16(acc[2 * np],     ah0, ah1, ah2, ah3, bh0, bh1);
            mma_bf16(acc[2 * np + 1], ah0, ah1, ah2, ah3, bh2, bh3);
            mma_bf16(acc[2 * np],     al0, al1, al2, al3, bh0, bh1);
            mma_bf16(acc[2 * np + 1], al0, al1, al2, al3, bh2, bh3);
            mma_bf16(acc[2 * np],     ah0, ah1, ah2, ah3, bl0, bl1);
            mma_bf16(acc[2 * np + 1], ah0, ah1, ah2, ah3, bl2, bl3);
        }
    }
}

__global__ __launch_bounds__(TLT, 2) void k_layer(const uint32_t* __restrict__ hinH,
                                                  const uint32_t* __restrict__ hinL,
                                                  uint32_t* __restrict__ houtH,
                                                  uint32_t* __restrict__ houtL,
                                                  const uint32_t* __restrict__ w1h,
                                                  const uint32_t* __restrict__ w1l,
                                                  const uint32_t* __restrict__ w2h,
                                                  const uint32_t* __restrict__ w2l,
                                                  int d) {
    extern __shared__ __align__(16) char smem[];
    uint32_t sb = smem_u32(smem);
    int tid = threadIdx.x;
    int wid = tid >> 5;
    int lid = tid & 31;
    int qr = lid >> 2;
    int qc = lid & 3;
    int b = blockIdx.y;
    int t0 = blockIdx.x * 128;

    // ---- stage A: vectorized copy; 768 copy-units of 64B (row,tap,arr)
    {
        const uint4 zero4 = make_uint4(0, 0, 0, 0);
#pragma unroll
        for (int u = 0; u < 3; u++) {
            int idx = tid + u * TLT;
            int m = idx / 6;
            int j = idx % 6;
            int tap = j >> 1;
            int arr = j & 1;
            int tt = t0 + m - (2 - tap) * d;
            uint32_t dst = (uint32_t)((arr ? SO_AL : SO_AH) + m * STRA + tap * 64);
            if (tt >= 0) {
                const uint32_t* src = (arr ? hinL : hinH) + (size_t)(b * TLEN + tt) * 16;
                const uint4* s4 = reinterpret_cast<const uint4*>(src);
#pragma unroll
                for (int q = 0; q < 4; q++)
                    *reinterpret_cast<uint4*>(smem + dst + q * 16) = s4[q];
            } else {
#pragma unroll
                for (int q = 0; q < 4; q++)
                    *reinterpret_cast<uint4*>(smem + dst + q * 16) = zero4;
            }
        }
    }
    // ---- weights: linear uint4 copies
    {
        const uint4* s1h = reinterpret_cast<const uint4*>(w1h);
        const uint4* s1l = reinterpret_cast<const uint4*>(w1l);
        uint4* d1h = reinterpret_cast<uint4*>(smem + SO_BH);
        uint4* d1l = reinterpret_cast<uint4*>(smem + SO_BL);
        for (int i = tid; i < 64 * 13; i += TLT) {
            d1h[i] = s1h[i];
            d1l[i] = s1l[i];
        }
        const uint4* s2h = reinterpret_cast<const uint4*>(w2h);
        const uint4* s2l = reinterpret_cast<const uint4*>(w2l);
        uint4* d2h = reinterpret_cast<uint4*>(smem + SO_W2H);
        uint4* d2l = reinterpret_cast<uint4*>(smem + SO_W2L);
        for (int i = tid; i < 64 * 5; i += TLT) {
            d2h[i] = s2h[i];
            d2l[i] = s2l[i];
        }
    }
    __syncthreads();

    // ---- conv GEMM: fused 3-combo
    float acc[8][4];
#pragma unroll
    for (int n = 0; n < 8; n++)
#pragma unroll
        for (int j = 0; j < 4; j++) acc[n][j] = 0.f;

    gemm_fused(sb + SO_AH, sb + SO_AL, sb + SO_BH, sb + SO_BL, STRA, 6, acc, wid, lid);

    // ---- gating entirely in registers -> A fragments for the 1x1 GEMM
    float gv[4][4];
#pragma unroll
    for (int n = 0; n < 4; n++)
#pragma unroll
        for (int j = 0; j < 4; j++)
            gv[n][j] = ftanh(acc[n][j]) * fsigm(acc[n + 4][j]);

    uint32_t aH[2][4], aL[2][4];
#pragma unroll
    for (int kk = 0; kk < 2; kk++) {
        split_pair(gv[2 * kk][0],     gv[2 * kk][1],     aH[kk][0], aL[kk][0]);
        split_pair(gv[2 * kk][2],     gv[2 * kk][3],     aH[kk][1], aL[kk][1]);
        split_pair(gv[2 * kk + 1][0], gv[2 * kk + 1][1], aH[kk][2], aL[kk][2]);
        split_pair(gv[2 * kk + 1][2], gv[2 * kk + 1][3], aH[kk][3], aL[kk][3]);
    }

    // ---- 1x1 GEMM: A from registers, B (W2) via ldmatrix; 3 combos
    float acc2[8][4];
#pragma unroll
    for (int n = 0; n < 8; n++)
#pragma unroll
        for (int j = 0; j < 4; j++) acc2[n][j] = 0.f;
    {
        int lr = lid & 7;
        int bRowOff = lr + (lid >> 4) * 8;
        int bKOff = ((lid >> 3) & 1) * 8;
        uint32_t w2H0 = sb + SO_W2H + (uint32_t)(bRowOff * STRG + bKOff * 2);
        uint32_t w2L0 = sb + SO_W2L + (uint32_t)(bRowOff * STRG + bKOff * 2);
#pragma unroll
        for (int kk = 0; kk < 2; kk++) {
            uint32_t ka = (uint32_t)(kk * 32);
#pragma unroll
            for (int np = 0; np < 4; np++) {
                uint32_t off = (uint32_t)(16 * np * STRG) + ka;
                uint32_t bh0, bh1, bh2, bh3, bl0, bl1, bl2, bl3;
                ldsm4(bh0, bh1, bh2, bh3, w2H0 + off);
                ldsm4(bl0, bl1, bl2, bl3, w2L0 + off);
                mma_bf16(acc2[2 * np],     aH[kk][0], aH[kk][1], aH[kk][2], aH[kk][3], bh0, bh1);
                mma_bf16(acc2[2 * np + 1], aH[kk][0], aH[kk][1], aH[kk][2], aH[kk][3], bh2, bh3);
                mma_bf16(acc2[2 * np],     aL[kk][0], aL[kk][1], aL[kk][2], aL[kk][3], bh0, bh1);
                mma_bf16(acc2[2 * np + 1], aL[kk][0], aL[kk][1], aL[kk][2], aL[kk][3], bh2, bh3);
                mma_bf16(acc2[2 * np],     aH[kk][0], aH[kk][1], aH[kk][2], aH[kk][3], bl0, bl1);
                mma_bf16(acc2[2 * np + 1], aH[kk][0], aH[kk][1], aH[kk][2], aH[kk][3], bl2, bl3);
            }
        }
    }

    // ---- epilogue phase A: compute hout hi/lo in registers (reads A tap2)
    uint32_t rhi[2][4], rlo[2][4];
#pragma unroll
    for (int rh = 0; rh < 2; rh++) {
        int rowA = 16 * wid + qr + 8 * rh;
#pragma unroll
        for (int n = 0; n < 4; n++) {
            int c = 8 * n + 2 * qc;
            uint32_t hh = *reinterpret_cast<uint32_t*>(smem + SO_AH + rowA * STRA + (64 + c) * 2);
            uint32_t ll = *reinterpret_cast<uint32_t*>(smem + SO_AL + rowA * STRA + (64 + c) * 2);
            float r0 = bfl(hh) + bfl(ll) + acc2[n][2 * rh + 0];
            float r1 = bfh(hh) + bfh(ll) + acc2[n][2 * rh + 1];
            split_pair(r0, r1, rhi[rh][n], rlo[rh][n]);
        }
    }
    __syncthreads();   // A/B regions now dead everywhere -> reuse for exchange

    // ---- epilogue phase B: STS into exchange buffers
#pragma unroll
    for (int rh = 0; rh < 2; rh++) {
        int rowA = 16 * wid + qr + 8 * rh;
#pragma unroll
        for (int n = 0; n < 4; n++) {
            uint32_t w = (uint32_t)(rowA * 20 + 4 * n + qc) * 4;
            sts32(sb + EXH + w, rhi[rh][n]);
            sts32(sb + EXL + w, rlo[rh][n]);
        }
#pragma unroll
        for (int n = 4; n < 8; n++) {
            int c = 8 * (n - 4) + 2 * qc;
            uint32_t w = (uint32_t)(rowA * 36 + c) * 4;
            sts64f(sb + EXS + w, acc2[n][2 * rh + 0], acc2[n][2 * rh + 1]);
        }
    }
    __syncthreads();

    // ---- epilogue phase C: coalesced copy-out
    {
        // hout planes: plane = tid>>7 (0=H,1=L); 512 uint4 per plane
        int plane = tid >> 7;
        int idx = tid & 127;
        uint32_t exb = sb + (plane ? EXL : EXH);
        uint32_t* gout = plane ? houtL : houtH;
        size_t gb4 = (size_t)(b * TLEN + t0) * 4;   // uint4 units
#pragma unroll
        for (int j = 0; j < 4; j++) {
            int g = idx + 128 * j;
            int row = g >> 2, q = g & 3;
            uint4 v;
            lds128(v, exb + (uint32_t)(row * 20 + q * 4) * 4);
            reinterpret_cast<uint4*>(gout)[gb4 + g] = v;
        }
        // skip RMW: 1024 float4 over 128 rows x 8; g = tid + 256*j
        float4* skb = reinterpret_cast<float4*>(g_skip + (size_t)(b * TLEN + t0) * 32);
#pragma unroll
        for (int j = 0; j < 4; j++) {
            int g = tid + 256 * j;
            int row = g >> 3, q = g & 7;
            uint4 zv;
            lds128(zv, sb + EXS + (uint32_t)(row * 36 + q * 4) * 4);
            float4 s = skb[g];
            s.x += __uint_as_float(zv.x);
            s.y += __uint_as_float(zv.y);
            s.z += __uint_as_float(zv.z);
            s.w += __uint_as_float(zv.w);
            skb[g] = s;
        }
    }
}

// ==================== tanh over skip (t-major -> channel-major) ============
__global__ __launch_bounds__(TT) void k_tanhskip() {
    int b = blockIdx.y;
    int t = blockIdx.x * TT + threadIdx.x;
    if (t >= TLEN) return;
    const float* sk = g_skip + (size_t)(b * TLEN + t) * 32;
#pragma unroll
    for (int c = 0; c < SKIPC; c++)
        g_ts[(b * SKIPC + c) * TLEN + t] = ftanh(sk[c]);
}

// ==================== generic causal k=3 conv + tanh =======================
template <int IC, int OC>
__global__ __launch_bounds__(TT) void k_conv3tanh(const float* __restrict__ in,
                                                  float* __restrict__ out,
                                                  const float* __restrict__ w) {
    __shared__ float ws[3][IC][OC];
    int tid = threadIdx.x;
    for (int i = tid; i < OC * IC * 3; i += TT) {
        int oc = i / (IC * 3), r = i % (IC * 3), ic = r / 3, k = r % 3;
        ws[k][ic][oc] = w[i];
    }
    __syncthreads();

    int b = blockIdx.y;
    int t = blockIdx.x * TT + tid;
    if (t >= TLEN) return;
    const float* ib = in + b * IC * TLEN;

    float acc[OC];
#pragma unroll
    for (int o = 0; o < OC; o++) acc[o] = 0.f;
#pragma unroll
    for (int k = 0; k < 3; k++) {
        int tt = t - (2 - k);
        if (tt >= 0) {
#pragma unroll
            for (int ic = 0; ic < IC; ic++) {
                float v = ib[ic * TLEN + tt];
#pragma unroll
                for (int o = 0; o < OC; o++)
                    acc[o] = fmaf(v, ws[k][ic][o], acc[o]);
            }
        }
    }
    float* ob = out + b * OC * TLEN;
#pragma unroll
    for (int o = 0; o < OC; o++)
        ob[o * TLEN + t] = ftanh(acc[o]);
}

// ==================== Volterra head ========================================
__global__ __launch_bounds__(TT) void k_vnn(const float* __restrict__ w1,
                                            const float* __restrict__ w2,
                                            float* __restrict__ out) {
    int b = blockIdx.y;
    int t = blockIdx.x * TT + threadIdx.x;
    if (t >= TLEN) return;
    const float* pb = g_p4 + b * TLEN;

    float pv[16];
#pragma unroll
    for (int k = 0; k < 16; k++) {
        int tt = t - (15 - k);
        pv[k] = (tt >= 0) ? pb[tt] : 0.f;
    }
    float lin = 0.f;
#pragma unroll
    for (int k = 0; k < 16; k++) lin = fmaf(w1[k], pv[k], lin);

    float x2[6];
#pragma unroll
    for (int j = 0; j < 6; j++) {
        float a = 0.f;
#pragma unroll
        for (int k = 0; k < 16; k++) a = fmaf(w2[j * 16 + k], pv[k], a);
        x2[j] = a;
    }
    float quad = x2[0] * x2[3] + x2[1] * x2[4] + x2[2] * x2[5];
    out[b * TLEN + t] = lin + quad;
}

// ==================== host launch ==========================================
extern "C" void kernel_launch(void* const* d_in, const int* in_sizes, int n_in,
                              void* d_out, int out_size) {
    const float* x       = (const float*)d_in[0];
    const float* conv1_w = (const float*)d_in[1];
    const float* res_w1  = (const float*)d_in[2];
    const float* res_w2  = (const float*)d_in[3];
    const float* post2_w = (const float*)d_in[4];
    const float* post3_w = (const float*)d_in[5];
    const float* post4_w = (const float*)d_in[6];
    const float* vnn1_w  = (const float*)d_in[7];
    const float* vnn2_w  = (const float*)d_in[8];
    float* out = (float*)d_out;

    uint32_t *bh0, *bl0, *bh1, *bl1;
    uint32_t *w1h, *w1l, *w2h, *w2l;
    float *tsp, *p2p, *p3p, *p4p;
    cudaGetSymbolAddress((void**)&bh0, g_bh0);
    cudaGetSymbolAddress((void**)&bl0, g_bl0);
    cudaGetSymbolAddress((void**)&bh1, g_bh1);
    cudaGetSymbolAddress((void**)&bl1, g_bl1);
    cudaGetSymbolAddress((void**)&w1h, g_w1h);
    cudaGetSymbolAddress((void**)&w1l, g_w1l);
    cudaGetSymbolAddress((void**)&w2h, g_w2h);
    cudaGetSymbolAddress((void**)&w2l, g_w2l);
    cudaGetSymbolAddress((void**)&tsp, g_ts);
    cudaGetSymbolAddress((void**)&p2p, g_p2);
    cudaGetSymbolAddress((void**)&p3p, g_p3);
    cudaGetSymbolAddress((void**)&p4p, g_p4);

    cudaFuncSetAttribute(k_layer, cudaFuncAttributeMaxDynamicSharedMemorySize,
                         SMEM_LAYER_BYTES);

    dim3 grid(TLEN / 128, BATCH);   // 250 x 8

    k_wprep<<<10, TT>>>(res_w1, res_w2);
    k_front<<<grid, TT>>>(x, conv1_w);

    const uint32_t *hinH = bh0, *hinL = bl0;
    uint32_t *houtH = bh1, *houtL = bl1;
    for (int s = 0; s < 2; s++) {
        for (int i = 0; i < 10; i++) {
            k_layer<<<grid, TLT, SMEM_LAYER_BYTES>>>(
                hinH, hinL, houtH, houtL,
                w1h + (size_t)i * 64 * 52, w1l + (size_t)i * 64 * 52,
                w2h + (size_t)i * 64 * 20, w2l + (size_t)i * 64 * 20,
                1 << i);
            const uint32_t* th = houtH; const uint32_t* tl = houtL;
            houtH = (uint32_t*)hinH; houtL = (uint32_t*)hinL;
            hinH = th; hinL = tl;
        }
    }

    k_tanhskip<<<grid, TT>>>();
    k_conv3tanh<32, 16><<<grid, TT>>>(tsp, p2p, post2_w);
    k_conv3tanh<16, 8><<<grid, TT>>>(p2p, p3p, post3_w);
    k_conv3tanh<8, 1><<<grid, TT>>>(p3p, p4p, post4_w);
    k_vnn<<<grid, TT>>>(vnn1_w, vnn2_w, out);
}

// round 15
// speedup vs baseline: 1.9060x; 1.2020x over previous
#include <cuda_runtime.h>
#include <math.h>
#include <stdint.h>

#define TLEN  32000
#define BATCH 8
#define RES   32
#define SKIPC 32
#define TT    128
#define TLT   256   // threads for k_layer (8 warps)

typedef unsigned long long ull;

// ==================== helpers ==============================================
__device__ __forceinline__ uint32_t smem_u32(const void* p) {
    uint32_t a;
    asm("{ .reg .u64 t; cvta.to.shared.u64 t, %1; cvt.u32.u64 %0, t; }" : "=r"(a) : "l"(p));
    return a;
}
__device__ __forceinline__ void sts32(uint32_t a, uint32_t v) {
    asm volatile("st.shared.b32 [%0], %1;" :: "r"(a), "r"(v));
}
__device__ __forceinline__ void sts64f(uint32_t a, float x, float y) {
    asm volatile("st.shared.v2.f32 [%0], {%1, %2};" :: "r"(a), "f"(x), "f"(y));
}
__device__ __forceinline__ void lds128(uint4& v, uint32_t a) {
    asm volatile("ld.shared.v4.b32 {%0,%1,%2,%3}, [%4];"
                 : "=r"(v.x), "=r"(v.y), "=r"(v.z), "=r"(v.w) : "r"(a));
}
__device__ __forceinline__ void ldsm4(uint32_t& r0, uint32_t& r1, uint32_t& r2, uint32_t& r3,
                                      uint32_t addr) {
    asm volatile("ldmatrix.sync.aligned.m8n8.x4.shared.b16 {%0,%1,%2,%3}, [%4];"
                 : "=r"(r0), "=r"(r1), "=r"(r2), "=r"(r3) : "r"(addr));
}
// pack {lo=v0, hi=v1} as bf16x2 (RN)
__device__ __forceinline__ uint32_t pack_bf16x2(float v0, float v1) {
    uint32_t r;
    asm("cvt.rn.bf16x2.f32 %0, %1, %2;" : "=r"(r) : "f"(v1), "f"(v0));
    return r;
}
__device__ __forceinline__ void mma_bf16(float* c,
                                         uint32_t a0, uint32_t a1, uint32_t a2, uint32_t a3,
                                         uint32_t b0, uint32_t b1) {
    asm volatile("mma.sync.aligned.m16n8k16.row.col.f32.bf16.bf16.f32 "
                 "{%0,%1,%2,%3}, {%4,%5,%6,%7}, {%8,%9}, {%0,%1,%2,%3};"
                 : "+f"(c[0]), "+f"(c[1]), "+f"(c[2]), "+f"(c[3])
                 : "r"(a0), "r"(a1), "r"(a2), "r"(a3), "r"(b0), "r"(b1));
}
__device__ __forceinline__ float ftanh(float x) {
    float e = __expf(-2.f * fabsf(x));
    float r = __fdividef(1.f - e, 1.f + e);
    return copysignf(r, x);
}
__device__ __forceinline__ float fsigm(float x) {
    return __fdividef(1.f, 1.f + __expf(-x));
}
// split pair into bf16 hi pack + residual lo pack
__device__ __forceinline__ void split_pair(float v0, float v1, uint32_t& hi, uint32_t& lo) {
    hi = pack_bf16x2(v0, v1);
    float h0 = __uint_as_float((hi & 0xFFFFu) << 16);
    float h1 = __uint_as_float(hi & 0xFFFF0000u);
    lo = pack_bf16x2(v0 - h0, v1 - h1);
}
__device__ __forceinline__ float bfl(uint32_t x) { return __uint_as_float(x << 16); }
__device__ __forceinline__ float bfh(uint32_t x) { return __uint_as_float(x & 0xFFFF0000u); }

// ==================== device scratch =======================================
__device__ uint32_t g_bh0[BATCH * TLEN * 16];
__device__ uint32_t g_bl0[BATCH * TLEN * 16];
__device__ uint32_t g_bh1[BATCH * TLEN * 16];
__device__ uint32_t g_bl1[BATCH * TLEN * 16];
__device__ float g_skip[BATCH * TLEN * SKIPC];   // time-major [b][t][32]
__device__ float g_ts[BATCH * SKIPC * TLEN];     // channel-major for post conv
__device__ float g_p2[BATCH * 16 * TLEN];
__device__ float g_p3[BATCH * 8 * TLEN];
__device__ float g_p4[BATCH * 1 * TLEN];
__device__ uint32_t g_w1h[10][64 * 52];
__device__ uint32_t g_w1l[10][64 * 52];
__device__ uint32_t g_w2h[10][64 * 20];
__device__ uint32_t g_w2l[10][64 * 20];

// ==================== weight prep ==========================================
__global__ __launch_bounds__(TT) void k_wprep(const float* __restrict__ res_w1,
                                              const float* __restrict__ res_w2) {
    int L = blockIdx.x;
    const float* w1 = res_w1 + (size_t)L * 64 * 32 * 3;
    const float* w2 = res_w2 + (size_t)L * 64 * 32;
    int tid = threadIdx.x;
    for (int i = tid; i < 64 * 48; i += TT) {
        int oc = i / 48, pj = i % 48;
        int k0 = 2 * pj;
        int tap = k0 >> 5, ic = k0 & 31;
        float v0 = w1[oc * 96 + ic * 3 + tap];
        float v1 = w1[oc * 96 + (ic + 1) * 3 + tap];
        uint32_t hi, lo;
        split_pair(v0, v1, hi, lo);
        g_w1h[L][oc * 52 + pj] = hi;
        g_w1l[L][oc * 52 + pj] = lo;
    }
    for (int i = tid; i < 64 * 16; i += TT) {
        int oc = i / 16, icp = i % 16;
        float v0 = w2[oc * 32 + 2 * icp];
        float v1 = w2[oc * 32 + 2 * icp + 1];
        uint32_t hi, lo;
        split_pair(v0, v1, hi, lo);
        g_w2h[L][oc * 20 + icp] = hi;
        g_w2l[L][oc * 20 + icp] = lo;
    }
}

// ==================== front conv -> bf16 hi/lo t-major; zero skip ==========
__global__ __launch_bounds__(TT) void k_front(const float* __restrict__ x,
                                              const float* __restrict__ w) {
    int b = blockIdx.y;
    int t = blockIdx.x * TT + threadIdx.x;
    if (t >= TLEN) return;
    const float* xb = x + b * TLEN;
    float x0 = xb[t];
    float x1 = (t >= 1) ? xb[t - 1] : 0.f;
    float x2 = (t >= 2) ? xb[t - 2] : 0.f;
    size_t base = (size_t)(b * TLEN + t) * 16;
    float* sk = g_skip + (size_t)(b * TLEN + t) * 32;
#pragma unroll
    for (int p = 0; p < 16; p++) {
        int oc = 2 * p;
        float v0 = fmaf(w[oc * 3 + 0], x2, fmaf(w[oc * 3 + 1], x1, w[oc * 3 + 2] * x0));
        float v1 = fmaf(w[(oc + 1) * 3 + 0], x2,
                   fmaf(w[(oc + 1) * 3 + 1], x1, w[(oc + 1) * 3 + 2] * x0));
        uint32_t hi, lo;
        split_pair(v0, v1, hi, lo);
        g_bh0[base + p] = hi;
        g_bl0[base + p] = lo;
        sk[oc] = 0.f;
        sk[oc + 1] = 0.f;
    }
}

// ==================== residual layer =======================================
// A window: one 64B row per time sample, stride 80B, max 384 rows per array.
#define STRW 80
#define STRB 208
#define SO_AH 0
#define SO_AL (384 * STRW)               // 30720
#define SO_BH (2 * 384 * STRW)           // 61440
#define SO_BL (SO_BH + 64 * STRB)        // 74752
#define SO_W2H (SO_BL + 64 * STRB)       // 88064
#define SO_W2L (SO_W2H + 64 * STRW)      // 93184
#define SMEM_LAYER_BYTES (SO_W2L + 64 * STRW)  // 98304
// exchange buffers (reuse of A space after epilogue sync)
#define EXH 0          // hout hi plane: 128 rows x 20 words = 10240
#define EXL 10240      // hout lo plane
#define EXS 20480      // skip z plane: 128 rows x 36 words = 18432

__global__ __launch_bounds__(TLT, 2) void k_layer(const uint32_t* __restrict__ hinH,
                                                  const uint32_t* __restrict__ hinL,
                                                  uint32_t* __restrict__ houtH,
                                                  uint32_t* __restrict__ houtL,
                                                  const uint32_t* __restrict__ w1h,
                                                  const uint32_t* __restrict__ w1l,
                                                  const uint32_t* __restrict__ w2h,
                                                  const uint32_t* __restrict__ w2l,
                                                  int d) {
    extern __shared__ __align__(16) char smem[];
    uint32_t sb = smem_u32(smem);
    int tid = threadIdx.x;
    int wid = tid >> 5;
    int lid = tid & 31;
    int qr = lid >> 2;
    int qc = lid & 3;
    int b = blockIdx.y;
    int t0 = blockIdx.x * 128;
    int dstep = (d <= 128) ? d : 128;
    int nrows = 128 + 2 * dstep;   // window rows (d<=128) or 3x128 segments

    // ---- stage A: window copy; units = nrows*2 of 64B (row, arr)
    {
        const uint4 zero4 = make_uint4(0, 0, 0, 0);
        int units = nrows * 2;
        for (int idx = tid; idx < units; idx += TLT) {
            int r = idx >> 1;
            int arr = idx & 1;
            int t;
            if (d <= 128) t = t0 - 2 * d + r;
            else          t = t0 - (2 - (r >> 7)) * d + (r & 127);
            uint32_t dst = (uint32_t)((arr ? SO_AL : SO_AH) + r * STRW);
            if (t >= 0) {
                const uint4* s4 = reinterpret_cast<const uint4*>(
                    (arr ? hinL : hinH) + (size_t)(b * TLEN + t) * 16);
#pragma unroll
                for (int q = 0; q < 4; q++)
                    *reinterpret_cast<uint4*>(smem + dst + q * 16) = s4[q];
            } else {
#pragma unroll
                for (int q = 0; q < 4; q++)
                    *reinterpret_cast<uint4*>(smem + dst + q * 16) = zero4;
            }
        }
    }
    // ---- weights: linear uint4 copies
    {
        const uint4* s1h = reinterpret_cast<const uint4*>(w1h);
        const uint4* s1l = reinterpret_cast<const uint4*>(w1l);
        uint4* d1h = reinterpret_cast<uint4*>(smem + SO_BH);
        uint4* d1l = reinterpret_cast<uint4*>(smem + SO_BL);
        for (int i = tid; i < 64 * 13; i += TLT) {
            d1h[i] = s1h[i];
            d1l[i] = s1l[i];
        }
        const uint4* s2h = reinterpret_cast<const uint4*>(w2h);
        const uint4* s2l = reinterpret_cast<const uint4*>(w2l);
        uint4* d2h = reinterpret_cast<uint4*>(smem + SO_W2H);
        uint4* d2l = reinterpret_cast<uint4*>(smem + SO_W2L);
        for (int i = tid; i < 64 * 5; i += TLT) {
            d2h[i] = s2h[i];
            d2l[i] = s2l[i];
        }
    }
    __syncthreads();

    // ---- conv GEMM: fused 3-combo, window A addressing
    float acc[8][4];
#pragma unroll
    for (int n = 0; n < 8; n++)
#pragma unroll
        for (int j = 0; j < 4; j++) acc[n][j] = 0.f;
    {
        int lr = lid & 7;
        int aRowOff = lr + ((lid >> 3) & 1) * 8;
        int aKOff = (lid >> 4) * 8;
        int bRowOff = lr + (lid >> 4) * 8;
        int bKOff = ((lid >> 3) & 1) * 8;
        uint32_t aBaseH = sb + SO_AH + (uint32_t)((16 * wid + aRowOff) * STRW + aKOff * 2);
        uint32_t aBaseL = sb + SO_AL + (uint32_t)((16 * wid + aRowOff) * STRW + aKOff * 2);
        uint32_t bH0 = sb + SO_BH + (uint32_t)(bRowOff * STRB + bKOff * 2);
        uint32_t bL0 = sb + SO_BL + (uint32_t)(bRowOff * STRB + bKOff * 2);
        uint32_t tapStride = (uint32_t)(dstep * STRW);
#pragma unroll
        for (int k = 0; k < 6; k++) {
            int tap = k >> 1;
            uint32_t aoff = (uint32_t)tap * tapStride + (uint32_t)((k & 1) * 32);
            uint32_t ka = (uint32_t)(k * 32);
            uint32_t ah0, ah1, ah2, ah3, al0, al1, al2, al3;
            ldsm4(ah0, ah1, ah2, ah3, aBaseH + aoff);
            ldsm4(al0, al1, al2, al3, aBaseL + aoff);
#pragma unroll
            for (int np = 0; np < 4; np++) {
                uint32_t off = (uint32_t)(16 * np * STRB) + ka;
                uint32_t bh0, bh1, bh2, bh3, bl0, bl1, bl2, bl3;
                ldsm4(bh0, bh1, bh2, bh3, bH0 + off);
                ldsm4(bl0, bl1, bl2, bl3, bL0 + off);
                mma_bf16(acc[2 * np],     ah0, ah1, ah2, ah3, bh0, bh1);
                mma_bf16(acc[2 * np + 1], ah0, ah1, ah2, ah3, bh2, bh3);
                mma_bf16(acc[2 * np],     al0, al1, al2, al3, bh0, bh1);
                mma_bf16(acc[2 * np + 1], al0, al1, al2, al3, bh2, bh3);
                mma_bf16(acc[2 * np],     ah0, ah1, ah2, ah3, bl0, bl1);
                mma_bf16(acc[2 * np + 1], ah0, ah1, ah2, ah3, bl2, bl3);
            }
        }
    }

    // ---- gating entirely in registers -> A fragments for the 1x1 GEMM
    float gv[4][4];
#pragma unroll
    for (int n = 0; n < 4; n++)
#pragma unroll
        for (int j = 0; j < 4; j++)
            gv[n][j] = ftanh(acc[n][j]) * fsigm(acc[n + 4][j]);

    uint32_t aH[2][4], aL[2][4];
#pragma unroll
    for (int kk = 0; kk < 2; kk++) {
        split_pair(gv[2 * kk][0],     gv[2 * kk][1],     aH[kk][0], aL[kk][0]);
        split_pair(gv[2 * kk][2],     gv[2 * kk][3],     aH[kk][1], aL[kk][1]);
        split_pair(gv[2 * kk + 1][0], gv[2 * kk + 1][1], aH[kk][2], aL[kk][2]);
        split_pair(gv[2 * kk + 1][2], gv[2 * kk + 1][3], aH[kk][3], aL[kk][3]);
    }

    // ---- 1x1 GEMM: A from registers, B (W2) via ldmatrix; 3 combos
    float acc2[8][4];
#pragma unroll
    for (int n = 0; n < 8; n++)
#pragma unroll
        for (int j = 0; j < 4; j++) acc2[n][j] = 0.f;
    {
        int lr = lid & 7;
        int bRowOff = lr + (lid >> 4) * 8;
        int bKOff = ((lid >> 3) & 1) * 8;
        uint32_t w2H0 = sb + SO_W2H + (uint32_t)(bRowOff * STRW + bKOff * 2);
        uint32_t w2L0 = sb + SO_W2L + (uint32_t)(bRowOff * STRW + bKOff * 2);
#pragma unroll
        for (int kk = 0; kk < 2; kk++) {
            uint32_t ka = (uint32_t)(kk * 32);
#pragma unroll
            for (int np = 0; np < 4; np++) {
                uint32_t off = (uint32_t)(16 * np * STRW) + ka;
                uint32_t bh0, bh1, bh2, bh3, bl0, bl1, bl2, bl3;
                ldsm4(bh0, bh1, bh2, bh3, w2H0 + off);
                ldsm4(bl0, bl1, bl2, bl3, w2L0 + off);
                mma_bf16(acc2[2 * np],     aH[kk][0], aH[kk][1], aH[kk][2], aH[kk][3], bh0, bh1);
                mma_bf16(acc2[2 * np + 1], aH[kk][0], aH[kk][1], aH[kk][2], aH[kk][3], bh2, bh3);
                mma_bf16(acc2[2 * np],     aL[kk][0], aL[kk][1], aL[kk][2], aL[kk][3], bh0, bh1);
                mma_bf16(acc2[2 * np + 1], aL[kk][0], aL[kk][1], aL[kk][2], aL[kk][3], bh2, bh3);
                mma_bf16(acc2[2 * np],     aH[kk][0], aH[kk][1], aH[kk][2], aH[kk][3], bl0, bl1);
                mma_bf16(acc2[2 * np + 1], aH[kk][0], aH[kk][1], aH[kk][2], aH[kk][3], bl2, bl3);
            }
        }
    }

    // ---- epilogue phase A: residual from window row (m + 2*dstep)
    uint32_t rhi[2][4], rlo[2][4];
#pragma unroll
    for (int rh = 0; rh < 2; rh++) {
        int rowA = 16 * wid + qr + 8 * rh;
        uint32_t rbase = (uint32_t)((rowA + 2 * dstep) * STRW);
#pragma unroll
        for (int n = 0; n < 4; n++) {
            int c = 8 * n + 2 * qc;
            uint32_t hh = *reinterpret_cast<uint32_t*>(smem + SO_AH + rbase + c * 2);
            uint32_t ll = *reinterpret_cast<uint32_t*>(smem + SO_AL + rbase + c * 2);
            float r0 = bfl(hh) + bfl(ll) + acc2[n][2 * rh + 0];
            float r1 = bfh(hh) + bfh(ll) + acc2[n][2 * rh + 1];
            split_pair(r0, r1, rhi[rh][n], rlo[rh][n]);
        }
    }
    __syncthreads();   // A region dead -> reuse for exchange

    // ---- epilogue phase B: STS into exchange buffers
#pragma unroll
    for (int rh = 0; rh < 2; rh++) {
        int rowA = 16 * wid + qr + 8 * rh;
#pragma unroll
        for (int n = 0; n < 4; n++) {
            uint32_t w = (uint32_t)(rowA * 20 + 4 * n + qc) * 4;
            sts32(sb + EXH + w, rhi[rh][n]);
            sts32(sb + EXL + w, rlo[rh][n]);
        }
#pragma unroll
        for (int n = 4; n < 8; n++) {
            int c = 8 * (n - 4) + 2 * qc;
            uint32_t w = (uint32_t)(rowA * 36 + c) * 4;
            sts64f(sb + EXS + w, acc2[n][2 * rh + 0], acc2[n][2 * rh + 1]);
        }
    }
    __syncthreads();

    // ---- epilogue phase C: coalesced copy-out
    {
        int plane = tid >> 7;
        int idx = tid & 127;
        uint32_t exb = sb + (plane ? EXL : EXH);
        uint32_t* gout = plane ? houtL : houtH;
        size_t gb4 = (size_t)(b * TLEN + t0) * 4;
#pragma unroll
        for (int j = 0; j < 4; j++) {
            int g = idx + 128 * j;
            int row = g >> 2, q = g & 3;
            uint4 v;
            lds128(v, exb + (uint32_t)(row * 20 + q * 4) * 4);
            reinterpret_cast<uint4*>(gout)[gb4 + g] = v;
        }
        float4* skb = reinterpret_cast<float4*>(g_skip + (size_t)(b * TLEN + t0) * 32);
#pragma unroll
        for (int j = 0; j < 4; j++) {
            int g = tid + 256 * j;
            int row = g >> 3, q = g & 7;
            uint4 zv;
            lds128(zv, sb + EXS + (uint32_t)(row * 36 + q * 4) * 4);
            float4 s = skb[g];
            s.x += __uint_as_float(zv.x);
            s.y += __uint_as_float(zv.y);
            s.z += __uint_as_float(zv.z);
            s.w += __uint_as_float(zv.w);
            skb[g] = s;
        }
    }
}

// ==================== tanh over skip (t-major -> channel-major) ============
__global__ __launch_bounds__(TT) void k_tanhskip() {
    int b = blockIdx.y;
    int t = blockIdx.x * TT + threadIdx.x;
    if (t >= TLEN) return;
    const float* sk = g_skip + (size_t)(b * TLEN + t) * 32;
#pragma unroll
    for (int c = 0; c < SKIPC; c++)
        g_ts[(b * SKIPC + c) * TLEN + t] = ftanh(sk[c]);
}

// ==================== generic causal k=3 conv + tanh =======================
template <int IC, int OC>
__global__ __launch_bounds__(TT) void k_conv3tanh(const float* __restrict__ in,
                                                  float* __restrict__ out,
                                                  const float* __restrict__ w) {
    __shared__ float ws[3][IC][OC];
    int tid = threadIdx.x;
    for (int i = tid; i < OC * IC * 3; i += TT) {
        int oc = i / (IC * 3), r = i % (IC * 3), ic = r / 3, k = r % 3;
        ws[k][ic][oc] = w[i];
    }
    __syncthreads();

    int b = blockIdx.y;
    int t = blockIdx.x * TT + tid;
    if (t >= TLEN) return;
    const float* ib = in + b * IC * TLEN;

    float acc[OC];
#pragma unroll
    for (int o = 0; o < OC; o++) acc[o] = 0.f;
#pragma unroll
    for (int k = 0; k < 3; k++) {
        int tt = t - (2 - k);
        if (tt >= 0) {
#pragma unroll
            for (int ic = 0; ic < IC; ic++) {
                float v = ib[ic * TLEN + tt];
#pragma unroll
                for (int o = 0; o < OC; o++)
                    acc[o] = fmaf(v, ws[k][ic][o], acc[o]);
            }
        }
    }
    float* ob = out + b * OC * TLEN;
#pragma unroll
    for (int o = 0; o < OC; o++)
        ob[o * TLEN + t] = ftanh(acc[o]);
}

// ==================== Volterra head ========================================
__global__ __launch_bounds__(TT) void k_vnn(const float* __restrict__ w1,
                                            const float* __restrict__ w2,
                                            float* __restrict__ out) {
    int b = blockIdx.y;
    int t = blockIdx.x * TT + threadIdx.x;
    if (t >= TLEN) return;
    const float* pb = g_p4 + b * TLEN;

    float pv[16];
#pragma unroll
    for (int k = 0; k < 16; k++) {
        int tt = t - (15 - k);
        pv[k] = (tt >= 0) ? pb[tt] : 0.f;
    }
    float lin = 0.f;
#pragma unroll
    for (int k = 0; k < 16; k++) lin = fmaf(w1[k], pv[k], lin);

    float x2[6];
#pragma unroll
    for (int j = 0; j < 6; j++) {
        float a = 0.f;
#pragma unroll
        for (int k = 0; k < 16; k++) a = fmaf(w2[j * 16 + k], pv[k], a);
        x2[j] = a;
    }
    float quad = x2[0] * x2[3] + x2[1] * x2[4] + x2[2] * x2[5];
    out[b * TLEN + t] = lin + quad;
}

// ==================== host launch ==========================================
extern "C" void kernel_launch(void* const* d_in, const int* in_sizes, int n_in,
                              void* d_out, int out_size) {
    const float* x       = (const float*)d_in[0];
    const float* conv1_w = (const float*)d_in[1];
    const float* res_w1  = (const float*)d_in[2];
    const float* res_w2  = (const float*)d_in[3];
    const float* post2_w = (const float*)d_in[4];
    const float* post3_w = (const float*)d_in[5];
    const float* post4_w = (const float*)d_in[6];
    const float* vnn1_w  = (const float*)d_in[7];
    const float* vnn2_w  = (const float*)d_in[8];
    float* out = (float*)d_out;

    uint32_t *bh0, *bl0, *bh1, *bl1;
    uint32_t *w1h, *w1l, *w2h, *w2l;
    float *tsp, *p2p, *p3p, *p4p;
    cudaGetSymbolAddress((void**)&bh0, g_bh0);
    cudaGetSymbolAddress((void**)&bl0, g_bl0);
    cudaGetSymbolAddress((void**)&bh1, g_bh1);
    cudaGetSymbolAddress((void**)&bl1, g_bl1);
    cudaGetSymbolAddress((void**)&w1h, g_w1h);
    cudaGetSymbolAddress((void**)&w1l, g_w1l);
    cudaGetSymbolAddress((void**)&w2h, g_w2h);
    cudaGetSymbolAddress((void**)&w2l, g_w2l);
    cudaGetSymbolAddress((void**)&tsp, g_ts);
    cudaGetSymbolAddress((void**)&p2p, g_p2);
    cudaGetSymbolAddress((void**)&p3p, g_p3);
    cudaGetSymbolAddress((void**)&p4p, g_p4);

    cudaFuncSetAttribute(k_layer, cudaFuncAttributeMaxDynamicSharedMemorySize,
                         SMEM_LAYER_BYTES);

    dim3 grid(TLEN / 128, BATCH);   // 250 x 8

    k_wprep<<<10, TT>>>(res_w1, res_w2);
    k_front<<<grid, TT>>>(x, conv1_w);

    const uint32_t *hinH = bh0, *hinL = bl0;
    uint32_t *houtH = bh1, *houtL = bl1;
    for (int s = 0; s < 2; s++) {
        for (int i = 0; i < 10; i++) {
            k_layer<<<grid, TLT, SMEM_LAYER_BYTES>>>(
                hinH, hinL, houtH, houtL,
                w1h + (size_t)i * 64 * 52, w1l + (size_t)i * 64 * 52,
                w2h + (size_t)i * 64 * 20, w2l + (size_t)i * 64 * 20,
                1 << i);
            const uint32_t* th = houtH; const uint32_t* tl = houtL;
            houtH = (uint32_t*)hinH; houtL = (uint32_t*)hinL;
            hinH = th; hinL = tl;
        }
    }

    k_tanhskip<<<grid, TT>>>();
    k_conv3tanh<32, 16><<<grid, TT>>>(tsp, p2p, post2_w);
    k_conv3tanh<16, 8><<<grid, TT>>>(p2p, p3p, post3_w);
    k_conv3tanh<8, 1><<<grid, TT>>>(p3p, p4p, post4_w);
    k_vnn<<<grid, TT>>>(vnn1_w, vnn2_w, out);
}

// round 16
// speedup vs baseline: 2.0513x; 1.0762x over previous
#include <cuda_runtime.h>
#include <math.h>
#include <stdint.h>

#define TLEN  32000
#define BATCH 8
#define RES   32
#define SKIPC 32
#define TT    128
#define TLT   256   // threads for k_layer (8 warps)

typedef unsigned long long ull;

// ==================== helpers ==============================================
__device__ __forceinline__ uint32_t smem_u32(const void* p) {
    uint32_t a;
    asm("{ .reg .u64 t; cvta.to.shared.u64 t, %1; cvt.u32.u64 %0, t; }" : "=r"(a) : "l"(p));
    return a;
}
__device__ __forceinline__ void sts32(uint32_t a, uint32_t v) {
    asm volatile("st.shared.b32 [%0], %1;" :: "r"(a), "r"(v));
}
__device__ __forceinline__ void sts64f(uint32_t a, float x, float y) {
    asm volatile("st.shared.v2.f32 [%0], {%1, %2};" :: "r"(a), "f"(x), "f"(y));
}
__device__ __forceinline__ void lds128(uint4& v, uint32_t a) {
    asm volatile("ld.shared.v4.b32 {%0,%1,%2,%3}, [%4];"
                 : "=r"(v.x), "=r"(v.y), "=r"(v.z), "=r"(v.w) : "r"(a));
}
__device__ __forceinline__ void ldsm4(uint32_t& r0, uint32_t& r1, uint32_t& r2, uint32_t& r3,
                                      uint32_t addr) {
    asm volatile("ldmatrix.sync.aligned.m8n8.x4.shared.b16 {%0,%1,%2,%3}, [%4];"
                 : "=r"(r0), "=r"(r1), "=r"(r2), "=r"(r3) : "r"(addr));
}
// pack {lo=v0, hi=v1} as bf16x2 (RN)
__device__ __forceinline__ uint32_t pack_bf16x2(float v0, float v1) {
    uint32_t r;
    asm("cvt.rn.bf16x2.f32 %0, %1, %2;" : "=r"(r) : "f"(v1), "f"(v0));
    return r;
}
__device__ __forceinline__ void mma_bf16(float* c,
                                         uint32_t a0, uint32_t a1, uint32_t a2, uint32_t a3,
                                         uint32_t b0, uint32_t b1) {
    asm volatile("mma.sync.aligned.m16n8k16.row.col.f32.bf16.bf16.f32 "
                 "{%0,%1,%2,%3}, {%4,%5,%6,%7}, {%8,%9}, {%0,%1,%2,%3};"
                 : "+f"(c[0]), "+f"(c[1]), "+f"(c[2]), "+f"(c[3])
                 : "r"(a0), "r"(a1), "r"(a2), "r"(a3), "r"(b0), "r"(b1));
}
__device__ __forceinline__ float ftanh(float x) {
    float e = __expf(-2.f * fabsf(x));
    float r = __fdividef(1.f - e, 1.f + e);
    return copysignf(r, x);
}
__device__ __forceinline__ float fsigm(float x) {
    return __fdividef(1.f, 1.f + __expf(-x));
}
// split pair into bf16 hi pack + residual lo pack
__device__ __forceinline__ void split_pair(float v0, float v1, uint32_t& hi, uint32_t& lo) {
    hi = pack_bf16x2(v0, v1);
    float h0 = __uint_as_float((hi & 0xFFFFu) << 16);
    float h1 = __uint_as_float(hi & 0xFFFF0000u);
    lo = pack_bf16x2(v0 - h0, v1 - h1);
}
__device__ __forceinline__ float bfl(uint32_t x) { return __uint_as_float(x << 16); }
__device__ __forceinline__ float bfh(uint32_t x) { return __uint_as_float(x & 0xFFFF0000u); }

// ==================== device scratch =======================================
__device__ uint32_t g_bh0[BATCH * TLEN * 16];
__device__ uint32_t g_bl0[BATCH * TLEN * 16];
__device__ uint32_t g_bh1[BATCH * TLEN * 16];
__device__ uint32_t g_bl1[BATCH * TLEN * 16];
__device__ float g_skip[BATCH * TLEN * SKIPC];   // time-major [b][t][32]
__device__ float g_ts[BATCH * SKIPC * TLEN];     // channel-major for post conv
__device__ float g_p2[BATCH * 16 * TLEN];
__device__ float g_p3[BATCH * 8 * TLEN];
__device__ float g_p4[BATCH * 1 * TLEN];
__device__ uint32_t g_w1h[10][64 * 52];
__device__ uint32_t g_w1l[10][64 * 52];
__device__ uint32_t g_w2h[10][64 * 20];
__device__ uint32_t g_w2l[10][64 * 20];

// ==================== weight prep ==========================================
__global__ __launch_bounds__(TT) void k_wprep(const float* __restrict__ res_w1,
                                              const float* __restrict__ res_w2) {
    int L = blockIdx.x;
    const float* w1 = res_w1 + (size_t)L * 64 * 32 * 3;
    const float* w2 = res_w2 + (size_t)L * 64 * 32;
    int tid = threadIdx.x;
    for (int i = tid; i < 64 * 48; i += TT) {
        int oc = i / 48, pj = i % 48;
        int k0 = 2 * pj;
        int tap = k0 >> 5, ic = k0 & 31;
        float v0 = w1[oc * 96 + ic * 3 + tap];
        float v1 = w1[oc * 96 + (ic + 1) * 3 + tap];
        uint32_t hi, lo;
        split_pair(v0, v1, hi, lo);
        g_w1h[L][oc * 52 + pj] = hi;
        g_w1l[L][oc * 52 + pj] = lo;
    }
    for (int i = tid; i < 64 * 16; i += TT) {
        int oc = i / 16, icp = i % 16;
        float v0 = w2[oc * 32 + 2 * icp];
        float v1 = w2[oc * 32 + 2 * icp + 1];
        uint32_t hi, lo;
        split_pair(v0, v1, hi, lo);
        g_w2h[L][oc * 20 + icp] = hi;
        g_w2l[L][oc * 20 + icp] = lo;
    }
}

// ==================== front conv -> bf16 hi/lo t-major; zero skip ==========
__global__ __launch_bounds__(TT) void k_front(const float* __restrict__ x,
                                              const float* __restrict__ w) {
    int b = blockIdx.y;
    int t = blockIdx.x * TT + threadIdx.x;
    if (t >= TLEN) return;
    const float* xb = x + b * TLEN;
    float x0 = xb[t];
    float x1 = (t >= 1) ? xb[t - 1] : 0.f;
    float x2 = (t >= 2) ? xb[t - 2] : 0.f;
    size_t base = (size_t)(b * TLEN + t) * 16;
    float* sk = g_skip + (size_t)(b * TLEN + t) * 32;
#pragma unroll
    for (int p = 0; p < 16; p++) {
        int oc = 2 * p;
        float v0 = fmaf(w[oc * 3 + 0], x2, fmaf(w[oc * 3 + 1], x1, w[oc * 3 + 2] * x0));
        float v1 = fmaf(w[(oc + 1) * 3 + 0], x2,
                   fmaf(w[(oc + 1) * 3 + 1], x1, w[(oc + 1) * 3 + 2] * x0));
        uint32_t hi, lo;
        split_pair(v0, v1, hi, lo);
        g_bh0[base + p] = hi;
        g_bl0[base + p] = lo;
        sk[oc] = 0.f;
        sk[oc + 1] = 0.f;
    }
}

// ==================== residual layer =======================================
// A window: one 64B row per time sample, stride 80B; offsets runtime-sized.
#define STRW 80
#define STRB 208
#define WB_BYTES (2 * 64 * STRB + 2 * 64 * STRW)   // 36864 (B hi/lo + W2 hi/lo)
// exchange buffers (reuse of front of smem after epilogue sync)
#define EXH 0          // hout hi plane: 128 rows x 20 words = 10240
#define EXL 10240      // hout lo plane
#define EXS 20480      // skip z plane: 128 rows x 36 words = 18432 (end 38912)

template <int MINB>
__global__ __launch_bounds__(TLT, MINB) void k_layer(const uint32_t* __restrict__ hinH,
                                                     const uint32_t* __restrict__ hinL,
                                                     uint32_t* __restrict__ houtH,
                                                     uint32_t* __restrict__ houtL,
                                                     const uint32_t* __restrict__ w1h,
                                                     const uint32_t* __restrict__ w1l,
                                                     const uint32_t* __restrict__ w2h,
                                                     const uint32_t* __restrict__ w2l,
                                                     int d) {
    extern __shared__ __align__(16) char smem[];
    uint32_t sb = smem_u32(smem);
    int tid = threadIdx.x;
    int wid = tid >> 5;
    int lid = tid & 31;
    int qr = lid >> 2;
    int qc = lid & 3;
    int b = blockIdx.y;
    int t0 = blockIdx.x * 128;
    int dstep = (d <= 128) ? d : 128;
    int nrows = 128 + 2 * dstep;
    uint32_t aBytes = (uint32_t)nrows * STRW;
    uint32_t oAL  = aBytes;
    uint32_t oBH  = 2 * aBytes;
    uint32_t oBL  = oBH + 64 * STRB;
    uint32_t oW2H = oBL + 64 * STRB;
    uint32_t oW2L = oW2H + 64 * STRW;

    // ---- stage A: window copy; units = nrows*2 of 64B (row, arr)
    {
        const uint4 zero4 = make_uint4(0, 0, 0, 0);
        int units = nrows * 2;
        for (int idx = tid; idx < units; idx += TLT) {
            int r = idx >> 1;
            int arr = idx & 1;
            int t;
            if (d <= 128) t = t0 - 2 * d + r;
            else          t = t0 - (2 - (r >> 7)) * d + (r & 127);
            uint32_t dst = (arr ? oAL : 0u) + (uint32_t)(r * STRW);
            if (t >= 0) {
                const uint4* s4 = reinterpret_cast<const uint4*>(
                    (arr ? hinL : hinH) + (size_t)(b * TLEN + t) * 16);
#pragma unroll
                for (int q = 0; q < 4; q++)
                    *reinterpret_cast<uint4*>(smem + dst + q * 16) = s4[q];
            } else {
#pragma unroll
                for (int q = 0; q < 4; q++)
                    *reinterpret_cast<uint4*>(smem + dst + q * 16) = zero4;
            }
        }
    }
    // ---- weights: linear uint4 copies
    {
        const uint4* s1h = reinterpret_cast<const uint4*>(w1h);
        const uint4* s1l = reinterpret_cast<const uint4*>(w1l);
        uint4* d1h = reinterpret_cast<uint4*>(smem + oBH);
        uint4* d1l = reinterpret_cast<uint4*>(smem + oBL);
        for (int i = tid; i < 64 * 13; i += TLT) {
            d1h[i] = s1h[i];
            d1l[i] = s1l[i];
        }
        const uint4* s2h = reinterpret_cast<const uint4*>(w2h);
        const uint4* s2l = reinterpret_cast<const uint4*>(w2l);
        uint4* d2h = reinterpret_cast<uint4*>(smem + oW2H);
        uint4* d2l = reinterpret_cast<uint4*>(smem + oW2L);
        for (int i = tid; i < 64 * 5; i += TLT) {
            d2h[i] = s2h[i];
            d2l[i] = s2l[i];
        }
    }
    __syncthreads();

    // ---- conv GEMM: fused 3-combo, window A addressing
    float acc[8][4];
#pragma unroll
    for (int n = 0; n < 8; n++)
#pragma unroll
        for (int j = 0; j < 4; j++) acc[n][j] = 0.f;
    {
        int lr = lid & 7;
        int aRowOff = lr + ((lid >> 3) & 1) * 8;
        int aKOff = (lid >> 4) * 8;
        int bRowOff = lr + (lid >> 4) * 8;
        int bKOff = ((lid >> 3) & 1) * 8;
        uint32_t aBaseH = sb + (uint32_t)((16 * wid + aRowOff) * STRW + aKOff * 2);
        uint32_t aBaseL = aBaseH + oAL;
        uint32_t bH0 = sb + oBH + (uint32_t)(bRowOff * STRB + bKOff * 2);
        uint32_t bL0 = sb + oBL + (uint32_t)(bRowOff * STRB + bKOff * 2);
        uint32_t tapStride = (uint32_t)(dstep * STRW);
#pragma unroll
        for (int k = 0; k < 6; k++) {
            int tap = k >> 1;
            uint32_t aoff = (uint32_t)tap * tapStride + (uint32_t)((k & 1) * 32);
            uint32_t ka = (uint32_t)(k * 32);
            uint32_t ah0, ah1, ah2, ah3, al0, al1, al2, al3;
            ldsm4(ah0, ah1, ah2, ah3, aBaseH + aoff);
            ldsm4(al0, al1, al2, al3, aBaseL + aoff);
#pragma unroll
            for (int np = 0; np < 4; np++) {
                uint32_t off = (uint32_t)(16 * np * STRB) + ka;
                uint32_t bh0, bh1, bh2, bh3, bl0, bl1, bl2, bl3;
                ldsm4(bh0, bh1, bh2, bh3, bH0 + off);
                ldsm4(bl0, bl1, bl2, bl3, bL0 + off);
                mma_bf16(acc[2 * np],     ah0, ah1, ah2, ah3, bh0, bh1);
                mma_bf16(acc[2 * np + 1], ah0, ah1, ah2, ah3, bh2, bh3);
                mma_bf16(acc[2 * np],     al0, al1, al2, al3, bh0, bh1);
                mma_bf16(acc[2 * np + 1], al0, al1, al2, al3, bh2, bh3);
                mma_bf16(acc[2 * np],     ah0, ah1, ah2, ah3, bl0, bl1);
                mma_bf16(acc[2 * np + 1], ah0, ah1, ah2, ah3, bl2, bl3);
            }
        }
    }

    // ---- gating entirely in registers -> A fragments for the 1x1 GEMM
    float gv[4][4];
#pragma unroll
    for (int n = 0; n < 4; n++)
#pragma unroll
        for (int j = 0; j < 4; j++)
            gv[n][j] = ftanh(acc[n][j]) * fsigm(acc[n + 4][j]);

    uint32_t aH[2][4], aL[2][4];
#pragma unroll
    for (int kk = 0; kk < 2; kk++) {
        split_pair(gv[2 * kk][0],     gv[2 * kk][1],     aH[kk][0], aL[kk][0]);
        split_pair(gv[2 * kk][2],     gv[2 * kk][3],     aH[kk][1], aL[kk][1]);
        split_pair(gv[2 * kk + 1][0], gv[2 * kk + 1][1], aH[kk][2], aL[kk][2]);
        split_pair(gv[2 * kk + 1][2], gv[2 * kk + 1][3], aH[kk][3], aL[kk][3]);
    }

    // ---- 1x1 GEMM: A from registers, B (W2) via ldmatrix; 3 combos
    float acc2[8][4];
#pragma unroll
    for (int n = 0; n < 8; n++)
#pragma unroll
        for (int j = 0; j < 4; j++) acc2[n][j] = 0.f;
    {
        int lr = lid & 7;
        int bRowOff = lr + (lid >> 4) * 8;
        int bKOff = ((lid >> 3) & 1) * 8;
        uint32_t w2H0 = sb + oW2H + (uint32_t)(bRowOff * STRW + bKOff * 2);
        uint32_t w2L0 = sb + oW2L + (uint32_t)(bRowOff * STRW + bKOff * 2);
#pragma unroll
        for (int kk = 0; kk < 2; kk++) {
            uint32_t ka = (uint32_t)(kk * 32);
#pragma unroll
            for (int np = 0; np < 4; np++) {
                uint32_t off = (uint32_t)(16 * np * STRW) + ka;
                uint32_t bh0, bh1, bh2, bh3, bl0, bl1, bl2, bl3;
                ldsm4(bh0, bh1, bh2, bh3, w2H0 + off);
                ldsm4(bl0, bl1, bl2, bl3, w2L0 + off);
                mma_bf16(acc2[2 * np],     aH[kk][0], aH[kk][1], aH[kk][2], aH[kk][3], bh0, bh1);
                mma_bf16(acc2[2 * np + 1], aH[kk][0], aH[kk][1], aH[kk][2], aH[kk][3], bh2, bh3);
                mma_bf16(acc2[2 * np],     aL[kk][0], aL[kk][1], aL[kk][2], aL[kk][3], bh0, bh1);
                mma_bf16(acc2[2 * np + 1], aL[kk][0], aL[kk][1], aL[kk][2], aL[kk][3], bh2, bh3);
                mma_bf16(acc2[2 * np],     aH[kk][0], aH[kk][1], aH[kk][2], aH[kk][3], bl0, bl1);
                mma_bf16(acc2[2 * np + 1], aH[kk][0], aH[kk][1], aH[kk][2], aH[kk][3], bl2, bl3);
            }
        }
    }

    // ---- epilogue phase A: residual from window row (m + 2*dstep)
    uint32_t rhi[2][4], rlo[2][4];
#pragma unroll
    for (int rh = 0; rh < 2; rh++) {
        int rowA = 16 * wid + qr + 8 * rh;
        uint32_t rbase = (uint32_t)((rowA + 2 * dstep) * STRW);
#pragma unroll
        for (int n = 0; n < 4; n++) {
            int c = 8 * n + 2 * qc;
            uint32_t hh = *reinterpret_cast<uint32_t*>(smem + rbase + c * 2);
            uint32_t ll = *reinterpret_cast<uint32_t*>(smem + oAL + rbase + c * 2);
            float r0 = bfl(hh) + bfl(ll) + acc2[n][2 * rh + 0];
            float r1 = bfh(hh) + bfh(ll) + acc2[n][2 * rh + 1];
            split_pair(r0, r1, rhi[rh][n], rlo[rh][n]);
        }
    }
    __syncthreads();   // whole smem dead -> reuse for exchange

    // ---- epilogue phase B: STS into exchange buffers
#pragma unroll
    for (int rh = 0; rh < 2; rh++) {
        int rowA = 16 * wid + qr + 8 * rh;
#pragma unroll
        for (int n = 0; n < 4; n++) {
            uint32_t w = (uint32_t)(rowA * 20 + 4 * n + qc) * 4;
            sts32(sb + EXH + w, rhi[rh][n]);
            sts32(sb + EXL + w, rlo[rh][n]);
        }
#pragma unroll
        for (int n = 4; n < 8; n++) {
            int c = 8 * (n - 4) + 2 * qc;
            uint32_t w = (uint32_t)(rowA * 36 + c) * 4;
            sts64f(sb + EXS + w, acc2[n][2 * rh + 0], acc2[n][2 * rh + 1]);
        }
    }
    __syncthreads();

    // ---- epilogue phase C: coalesced copy-out
    {
        int plane = tid >> 7;
        int idx = tid & 127;
        uint32_t exb = sb + (plane ? EXL : EXH);
        uint32_t* gout = plane ? houtL : houtH;
        size_t gb4 = (size_t)(b * TLEN + t0) * 4;
#pragma unroll
        for (int j = 0; j < 4; j++) {
            int g = idx + 128 * j;
            int row = g >> 2, q = g & 3;
            uint4 v;
            lds128(v, exb + (uint32_t)(row * 20 + q * 4) * 4);
            reinterpret_cast<uint4*>(gout)[gb4 + g] = v;
        }
        float4* skb = reinterpret_cast<float4*>(g_skip + (size_t)(b * TLEN + t0) * 32);
#pragma unroll
        for (int j = 0; j < 4; j++) {
            int g = tid + 256 * j;
            int row = g >> 3, q = g & 7;
            uint4 zv;
            lds128(zv, sb + EXS + (uint32_t)(row * 36 + q * 4) * 4);
            float4 s = skb[g];
            s.x += __uint_as_float(zv.x);
            s.y += __uint_as_float(zv.y);
            s.z += __uint_as_float(zv.z);
            s.w += __uint_as_float(zv.w);
            skb[g] = s;
        }
    }
}

// ==================== tanh over skip (t-major -> channel-major) ============
__global__ __launch_bounds__(TT) void k_tanhskip() {
    int b = blockIdx.y;
    int t = blockIdx.x * TT + threadIdx.x;
    if (t >= TLEN) return;
    const float* sk = g_skip + (size_t)(b * TLEN + t) * 32;
#pragma unroll
    for (int c = 0; c < SKIPC; c++)
        g_ts[(b * SKIPC + c) * TLEN + t] = ftanh(sk[c]);
}

// ==================== generic causal k=3 conv + tanh =======================
template <int IC, int OC>
__global__ __launch_bounds__(TT) void k_conv3tanh(const float* __restrict__ in,
                                                  float* __restrict__ out,
                                                  const float* __restrict__ w) {
    __shared__ float ws[3][IC][OC];
    int tid = threadIdx.x;
    for (int i = tid; i < OC * IC * 3; i += TT) {
        int oc = i / (IC * 3), r = i % (IC * 3), ic = r / 3, k = r % 3;
        ws[k][ic][oc] = w[i];
    }
    __syncthreads();

    int b = blockIdx.y;
    int t = blockIdx.x * TT + tid;
    if (t >= TLEN) return;
    const float* ib = in + b * IC * TLEN;

    float acc[OC];
#pragma unroll
    for (int o = 0; o < OC; o++) acc[o] = 0.f;
#pragma unroll
    for (int k = 0; k < 3; k++) {
        int tt = t - (2 - k);
        if (tt >= 0) {
#pragma unroll
            for (int ic = 0; ic < IC; ic++) {
                float v = ib[ic * TLEN + tt];
#pragma unroll
                for (int o = 0; o < OC; o++)
                    acc[o] = fmaf(v, ws[k][ic][o], acc[o]);
            }
        }
    }
    float* ob = out + b * OC * TLEN;
#pragma unroll
    for (int o = 0; o < OC; o++)
        ob[o * TLEN + t] = ftanh(acc[o]);
}

// ==================== Volterra head ========================================
__global__ __launch_bounds__(TT) void k_vnn(const float* __restrict__ w1,
                                            const float* __restrict__ w2,
                                            float* __restrict__ out) {
    int b = blockIdx.y;
    int t = blockIdx.x * TT + threadIdx.x;
    if (t >= TLEN) return;
    const float* pb = g_p4 + b * TLEN;

    float pv[16];
#pragma unroll
    for (int k = 0; k < 16; k++) {
        int tt = t - (15 - k);
        pv[k] = (tt >= 0) ? pb[tt] : 0.f;
    }
    float lin = 0.f;
#pragma unroll
    for (int k = 0; k < 16; k++) lin = fmaf(w1[k], pv[k], lin);

    float x2[6];
#pragma unroll
    for (int j = 0; j < 6; j++) {
        float a = 0.f;
#pragma unroll
        for (int k = 0; k < 16; k++) a = fmaf(w2[j * 16 + k], pv[k], a);
        x2[j] = a;
    }
    float quad = x2[0] * x2[3] + x2[1] * x2[4] + x2[2] * x2[5];
    out[b * TLEN + t] = lin + quad;
}

// ==================== host launch ==========================================
extern "C" void kernel_launch(void* const* d_in, const int* in_sizes, int n_in,
                              void* d_out, int out_size) {
    const float* x       = (const float*)d_in[0];
    const float* conv1_w = (const float*)d_in[1];
    const float* res_w1  = (const float*)d_in[2];
    const float* res_w2  = (const float*)d_in[3];
    const float* post2_w = (const float*)d_in[4];
    const float* post3_w = (const float*)d_in[5];
    const float* post4_w = (const float*)d_in[6];
    const float* vnn1_w  = (const float*)d_in[7];
    const float* vnn2_w  = (const float*)d_in[8];
    float* out = (float*)d_out;

    uint32_t *bh0, *bl0, *bh1, *bl1;
    uint32_t *w1h, *w1l, *w2h, *w2l;
    float *tsp, *p2p, *p3p, *p4p;
    cudaGetSymbolAddress((void**)&bh0, g_bh0);
    cudaGetSymbolAddress((void**)&bl0, g_bl0);
    cudaGetSymbolAddress((void**)&bh1, g_bh1);
    cudaGetSymbolAddress((void**)&bl1, g_bl1);
    cudaGetSymbolAddress((void**)&w1h, g_w1h);
    cudaGetSymbolAddress((void**)&w1l, g_w1l);
    cudaGetSymbolAddress((void**)&w2h, g_w2h);
    cudaGetSymbolAddress((void**)&w2l, g_w2l);
    cudaGetSymbolAddress((void**)&tsp, g_ts);
    cudaGetSymbolAddress((void**)&p2p, g_p2);
    cudaGetSymbolAddress((void**)&p3p, g_p3);
    cudaGetSymbolAddress((void**)&p4p, g_p4);

    // max dynamic smem for each instantiation
    cudaFuncSetAttribute(k_layer<2>, cudaFuncAttributeMaxDynamicSharedMemorySize,
                         160 * 384 + WB_BYTES);           // 98304
    cudaFuncSetAttribute(k_layer<3>, cudaFuncAttributeMaxDynamicSharedMemorySize,
                         160 * (128 + 64) + WB_BYTES);    // d<=32 -> 67584

    dim3 grid(TLEN / 128, BATCH);   // 250 x 8

    k_wprep<<<10, TT>>>(res_w1, res_w2);
    k_front<<<grid, TT>>>(x, conv1_w);

    const uint32_t *hinH = bh0, *hinL = bl0;
    uint32_t *houtH = bh1, *houtL = bl1;
    for (int s = 0; s < 2; s++) {
        for (int i = 0; i < 10; i++) {
            int d = 1 << i;
            int dstep = (d <= 128) ? d : 128;
            int nrows = 128 + 2 * dstep;
            size_t smemBytes = (size_t)160 * nrows + WB_BYTES;
            const uint32_t* a1 = w1h + (size_t)i * 64 * 52;
            const uint32_t* a2 = w1l + (size_t)i * 64 * 52;
            const uint32_t* a3 = w2h + (size_t)i * 64 * 20;
            const uint32_t* a4 = w2l + (size_t)i * 64 * 20;
            if (d <= 32) {
                k_layer<3><<<grid, TLT, smemBytes>>>(hinH, hinL, houtH, houtL,
                                                     a1, a2, a3, a4, d);
            } else {
                k_layer<2><<<grid, TLT, smemBytes>>>(hinH, hinL, houtH, houtL,
                                                     a1, a2, a3, a4, d);
            }
            const uint32_t* th = houtH; const uint32_t* tl = houtL;
            houtH = (uint32_t*)hinH; houtL = (uint32_t*)hinL;
            hinH = th; hinL = tl;
        }
    }

    k_tanhskip<<<grid, TT>>>();
    k_conv3tanh<32, 16><<<grid, TT>>>(tsp, p2p, post2_w);
    k_conv3tanh<16, 8><<<grid, TT>>>(p2p, p3p, post3_w);
    k_conv3tanh<8, 1><<<grid, TT>>>(p3p, p4p, post4_w);
    k_vnn<<<grid, TT>>>(vnn1_w, vnn2_w, out);
}